// round 2
// baseline (speedup 1.0000x reference)
#include <cuda_runtime.h>
#include <cuda_bf16.h>
#include <math.h>

// Problem constants
#define NUM_ENVS   16384
#define NUM_AGENTS 16
#define IN_DIM     128
#define GCN_H      64
#define RNN_H      64
#define E_PER_G    128
#define OUT_DIM    512           // 16*4*8
#define FLAT_DIM   1024          // NUM_AGENTS * RNN_H

// Scratch for h_new in case d_out only holds logits. 64 MB static — allowed.
__device__ float g_h[(size_t)NUM_ENVS * FLAT_DIM];

// ---------------------------------------------------------------------------
// Kernel 1: fused GCN + GRU, one block per env, 128 threads.
// a = tid>>3 (agent 0..15), jb = (tid&7)*8 (8-wide column slice).
// ---------------------------------------------------------------------------
__global__ __launch_bounds__(128)
void fused_gcn_gru_kernel(const float* __restrict__ x,
                          const int* __restrict__ ei,      // int32! (JAX x64 off)
                          const float* __restrict__ ph,
                          const float* __restrict__ Wg,
                          const float* __restrict__ bg,
                          const float* __restrict__ Wih,
                          const float* __restrict__ Whh,
                          const float* __restrict__ bih,
                          const float* __restrict__ bhh,
                          float* hout)                     // may be null -> g_h
{
    const int env = blockIdx.x;
    const int tid = threadIdx.x;
    float* hdst = hout ? hout : g_h;

    __shared__ float sx[NUM_AGENTS][136];   // x rows
    __shared__ float sxw[NUM_AGENTS][68];   // x @ W_gcn
    __shared__ float sgcn[NUM_AGENTS][68];  // gcn output
    __shared__ float sh[NUM_AGENTS][68];    // prev hidden
    __shared__ float sdeg[NUM_AGENTS];
    __shared__ float snorm[E_PER_G];
    __shared__ int   srow[E_PER_G];
    __shared__ int   scol[E_PER_G];

    // ---- cooperative loads -------------------------------------------------
    {
        const float4* xg = (const float4*)(x + (size_t)env * NUM_AGENTS * IN_DIM);
        for (int i = tid; i < NUM_AGENTS * IN_DIM / 4; i += 128) {
            int a = i >> 5;
            int q = i & 31;
            *(float4*)&sx[a][q * 4] = xg[i];
        }
        const float4* hg = (const float4*)(ph + (size_t)env * FLAT_DIM);
        for (int i = tid; i < FLAT_DIM / 4; i += 128) {
            int a = i >> 4;
            int q = i & 15;
            *(float4*)&sh[a][q * 4] = hg[i];
        }
        const int* eg = ei + (size_t)env * 2 * E_PER_G;
        srow[tid] = eg[tid] & 15;             // ei[env][0][e] (defensive mask)
        scol[tid] = eg[E_PER_G + tid] & 15;   // ei[env][1][e]
        if (tid < NUM_AGENTS) sdeg[tid] = 1.0f;  // self-loop
    }
    __syncthreads();

    // ---- degrees -----------------------------------------------------------
    atomicAdd(&sdeg[scol[tid]], 1.0f);
    __syncthreads();

    // ---- edge norms --------------------------------------------------------
    snorm[tid] = rsqrtf(sdeg[srow[tid]] * sdeg[scol[tid]]);

    const int a  = tid >> 3;
    const int jb = (tid & 7) * 8;

    // ---- xw = x_row(a) @ W_gcn[:, jb..jb+7] --------------------------------
    {
        float acc[8];
        #pragma unroll
        for (int j = 0; j < 8; j++) acc[j] = 0.0f;
        for (int k = 0; k < IN_DIM; k += 4) {
            float4 xv = *(const float4*)&sx[a][k];
            float xs[4] = {xv.x, xv.y, xv.z, xv.w};
            #pragma unroll
            for (int q = 0; q < 4; q++) {
                const float* wrow = Wg + (k + q) * GCN_H + jb;
                float4 w0 = __ldg((const float4*)wrow);
                float4 w1 = __ldg((const float4*)(wrow + 4));
                acc[0] += xs[q] * w0.x;  acc[1] += xs[q] * w0.y;
                acc[2] += xs[q] * w0.z;  acc[3] += xs[q] * w0.w;
                acc[4] += xs[q] * w1.x;  acc[5] += xs[q] * w1.y;
                acc[6] += xs[q] * w1.z;  acc[7] += xs[q] * w1.w;
            }
        }
        #pragma unroll
        for (int j = 0; j < 8; j++) sxw[a][jb + j] = acc[j];
    }
    __syncthreads();

    // ---- scatter: owner-computes (no atomics) ------------------------------
    {
        float gacc[8];
        #pragma unroll
        for (int j = 0; j < 8; j++) gacc[j] = 0.0f;
        for (int e = 0; e < E_PER_G; e++) {
            if (scol[e] == a) {
                float nm = snorm[e];
                const float* src = &sxw[srow[e]][jb];
                float4 s0 = *(const float4*)src;
                float4 s1 = *(const float4*)(src + 4);
                gacc[0] += nm * s0.x;  gacc[1] += nm * s0.y;
                gacc[2] += nm * s0.z;  gacc[3] += nm * s0.w;
                gacc[4] += nm * s1.x;  gacc[5] += nm * s1.y;
                gacc[6] += nm * s1.z;  gacc[7] += nm * s1.w;
            }
        }
        float invd = 1.0f / sdeg[a];
        #pragma unroll
        for (int j = 0; j < 8; j++)
            sgcn[a][jb + j] = gacc[j] + sxw[a][jb + j] * invd + __ldg(&bg[jb + j]);
    }
    __syncthreads();

    // ---- GRU ----------------------------------------------------------------
    {
        const int hb = jb;
        float accx[3][8], acch[3][8];
        #pragma unroll
        for (int g = 0; g < 3; g++) {
            #pragma unroll
            for (int j = 0; j < 8; j++) {
                accx[g][j] = __ldg(&bih[g * 64 + hb + j]);
                acch[g][j] = __ldg(&bhh[g * 64 + hb + j]);
            }
        }
        for (int k = 0; k < RNN_H; k += 4) {
            float4 xv = *(const float4*)&sgcn[a][k];
            float4 hv = *(const float4*)&sh[a][k];
            #pragma unroll
            for (int g = 0; g < 3; g++) {
                #pragma unroll
                for (int j = 0; j < 8; j++) {
                    int row = g * 64 + hb + j;
                    float4 wi = __ldg((const float4*)(Wih + row * 64 + k));
                    accx[g][j] += xv.x * wi.x + xv.y * wi.y + xv.z * wi.z + xv.w * wi.w;
                    float4 wh = __ldg((const float4*)(Whh + row * 64 + k));
                    acch[g][j] += hv.x * wh.x + hv.y * wh.y + hv.z * wh.z + hv.w * wh.w;
                }
            }
        }

        float hnew[8];
        #pragma unroll
        for (int j = 0; j < 8; j++) {
            float r = 1.0f / (1.0f + expf(-(accx[0][j] + acch[0][j])));
            float z = 1.0f / (1.0f + expf(-(accx[1][j] + acch[1][j])));
            float n = tanhf(accx[2][j] + r * acch[2][j]);
            float hp = sh[a][hb + j];
            hnew[j] = (1.0f - z) * n + z * hp;
        }
        float4* dst = (float4*)(hdst + (size_t)env * FLAT_DIM + a * RNN_H + hb);
        dst[0] = make_float4(hnew[0], hnew[1], hnew[2], hnew[3]);
        dst[1] = make_float4(hnew[4], hnew[5], hnew[6], hnew[7]);
    }
}

// ---------------------------------------------------------------------------
// Kernel 2: logits = h_flat[16384,1024] @ W_lin^T[1024,512] + b_lin
// ---------------------------------------------------------------------------
#define BM 64
#define BN 64
#define BK 16

__global__ __launch_bounds__(256)
void logits_gemm_kernel(const float* A_in,                // may be null -> g_h
                        const float* __restrict__ W,      // [512, 1024]
                        const float* __restrict__ bias,   // [512]
                        float* __restrict__ C)            // [16384, 512]
{
    const float* __restrict__ A = A_in ? A_in : (const float*)g_h;

    __shared__ float As[BM][BK + 1];
    __shared__ float Bs[BN][BK + 1];

    const int bm = blockIdx.x * BM;
    const int bn = blockIdx.y * BN;
    const int tid = threadIdx.x;
    const int tx = tid & 15;
    const int ty = tid >> 4;

    float acc[4][4];
    #pragma unroll
    for (int i = 0; i < 4; i++)
        #pragma unroll
        for (int j = 0; j < 4; j++) acc[i][j] = 0.0f;

    const int lr = tid >> 2;
    const int lk = (tid & 3) * 4;

    for (int k0 = 0; k0 < FLAT_DIM; k0 += BK) {
        float4 va = __ldg((const float4*)(A + (size_t)(bm + lr) * FLAT_DIM + k0 + lk));
        float4 vb = __ldg((const float4*)(W + (size_t)(bn + lr) * FLAT_DIM + k0 + lk));
        As[lr][lk] = va.x; As[lr][lk + 1] = va.y; As[lr][lk + 2] = va.z; As[lr][lk + 3] = va.w;
        Bs[lr][lk] = vb.x; Bs[lr][lk + 1] = vb.y; Bs[lr][lk + 2] = vb.z; Bs[lr][lk + 3] = vb.w;
        __syncthreads();

        #pragma unroll
        for (int k = 0; k < BK; k++) {
            float av[4], bv[4];
            #pragma unroll
            for (int i = 0; i < 4; i++) av[i] = As[ty * 4 + i][k];
            #pragma unroll
            for (int j = 0; j < 4; j++) bv[j] = Bs[tx * 4 + j][k];
            #pragma unroll
            for (int i = 0; i < 4; i++)
                #pragma unroll
                for (int j = 0; j < 4; j++)
                    acc[i][j] += av[i] * bv[j];
        }
        __syncthreads();
    }

    #pragma unroll
    for (int i = 0; i < 4; i++) {
        float4 o;
        o.x = acc[i][0] + __ldg(&bias[bn + tx * 4 + 0]);
        o.y = acc[i][1] + __ldg(&bias[bn + tx * 4 + 1]);
        o.z = acc[i][2] + __ldg(&bias[bn + tx * 4 + 2]);
        o.w = acc[i][3] + __ldg(&bias[bn + tx * 4 + 3]);
        *(float4*)(C + (size_t)(bm + ty * 4 + i) * OUT_DIM + bn + tx * 4) = o;
    }
}

// ---------------------------------------------------------------------------
extern "C" void kernel_launch(void* const* d_in, const int* in_sizes, int n_in,
                              void* d_out, int out_size)
{
    const float* x    = (const float*)d_in[0];
    const int*   ei   = (const int*)d_in[1];      // int32 (JAX x64 disabled)
    const float* ph   = (const float*)d_in[2];
    const float* Wg   = (const float*)d_in[3];
    const float* bg   = (const float*)d_in[4];
    const float* Wih  = (const float*)d_in[5];
    const float* Whh  = (const float*)d_in[6];
    const float* bih  = (const float*)d_in[7];
    const float* bhh  = (const float*)d_in[8];
    const float* Wlin = (const float*)d_in[9];
    const float* blin = (const float*)d_in[10];

    float* out    = (float*)d_out;
    float* logits = out;                                  // [16384, 512]

    // If d_out also holds next_h (tuple output concatenated), write h there;
    // otherwise keep it in the device scratch g_h (null sentinel).
    const long long need = (long long)NUM_ENVS * (OUT_DIM + FLAT_DIM);
    float* hout = ((long long)out_size >= need)
                      ? out + (size_t)NUM_ENVS * OUT_DIM
                      : nullptr;

    fused_gcn_gru_kernel<<<NUM_ENVS, 128>>>(x, ei, ph, Wg, bg, Wih, Whh,
                                            bih, bhh, hout);

    dim3 g2(NUM_ENVS / BM, OUT_DIM / BN);
    logits_gemm_kernel<<<g2, 256>>>(hout, Wlin, blin, logits);
}

// round 3
// speedup vs baseline: 4.1701x; 4.1701x over previous
#include <cuda_runtime.h>
#include <cuda_bf16.h>
#include <math.h>

// Problem constants
#define NUM_ENVS   16384
#define NUM_AGENTS 16
#define IN_DIM     128
#define GCN_H      64
#define RNN_H      64
#define E_PER_G    128
#define OUT_DIM    512           // 16*4*8
#define FLAT_DIM   1024          // NUM_AGENTS * RNN_H
#define N_NODES    ((size_t)NUM_ENVS * NUM_AGENTS)   // 262144

// ---- device scratch (static; no runtime allocation) -----------------------
__device__ float g_xw [N_NODES * GCN_H];       // 67 MB  x @ W_gcn
__device__ float g_gcn[N_NODES * GCN_H];       // 67 MB  gcn output
__device__ float g_G  [N_NODES * 256];         // 268 MB gate pre-activations
__device__ float g_h  [N_NODES * RNN_H];       // 67 MB  h_new (if not in d_out)
__device__ float g_WgT [GCN_H * IN_DIM];       // [64][128]  W_gcn transposed
__device__ float g_B2  [256 * 128];            // fused GRU weights [256][128]
__device__ float g_bias2[256];

// ---------------------------------------------------------------------------
// Prep: transpose W_gcn, build fused GRU weight matrix B2 + bias2.
// B2 row n (output col), col k (input of [gcn | h]):
//   n in [0,128)  : r/z rows  -> Wih[n][k] for k<64, Whh[n][k-64] otherwise
//   n in [128,192): n_x rows  -> Wih[n][k] for k<64, 0 otherwise
//   n in [192,256): n_h rows  -> 0 for k<64, Whh[n-64][k-64] otherwise
// ---------------------------------------------------------------------------
__global__ void prep_kernel(const float* __restrict__ Wg,
                            const float* __restrict__ Wih,
                            const float* __restrict__ Whh,
                            const float* __restrict__ bih,
                            const float* __restrict__ bhh)
{
    const int n = threadIdx.x;   // 0..255
    if (n < GCN_H) {
        for (int k = 0; k < IN_DIM; k++)
            g_WgT[n * IN_DIM + k] = Wg[k * GCN_H + n];
    }
    if (n < 128) {
        for (int k = 0; k < 64;  k++) g_B2[n * 128 + k]      = Wih[n * 64 + k];
        for (int k = 0; k < 64;  k++) g_B2[n * 128 + 64 + k] = Whh[n * 64 + k];
        g_bias2[n] = bih[n] + bhh[n];
    } else if (n < 192) {
        for (int k = 0; k < 64;  k++) g_B2[n * 128 + k]      = Wih[n * 64 + k];
        for (int k = 0; k < 64;  k++) g_B2[n * 128 + 64 + k] = 0.0f;
        g_bias2[n] = bih[n];
    } else {
        const int m = n - 64;    // Whh row 128..191
        for (int k = 0; k < 64;  k++) g_B2[n * 128 + k]      = 0.0f;
        for (int k = 0; k < 64;  k++) g_B2[n * 128 + 64 + k] = Whh[m * 64 + k];
        g_bias2[n] = bhh[m];
    }
}

// ---------------------------------------------------------------------------
// Generic GEMM: C[M,N] = [A0 | A1] @ W^T + bias
//   A is split at k=64: k<64 reads A0[row*ldA0 + k], k>=64 reads
//   A1[row*ldA1 + k-64].  (For an unsplit matrix pass A1 = A0+64, ldA1=ldA0.)
//   W row-major [N][K].  BM=BN=64, BK=16, 256 threads, 4x4 microtile.
// ---------------------------------------------------------------------------
#define BM 64
#define BN 64
#define BK 16

__global__ __launch_bounds__(256)
void gemm_kernel(const float* __restrict__ A0, int ldA0,
                 const float* __restrict__ A1, int ldA1,
                 const float* __restrict__ W,  int K,
                 const float* __restrict__ bias,
                 float* __restrict__ C, int ldC)
{
    __shared__ float As[BM][BK + 1];
    __shared__ float Bs[BN][BK + 1];

    const int bm = blockIdx.x * BM;
    const int bn = blockIdx.y * BN;
    const int tid = threadIdx.x;
    const int tx = tid & 15;
    const int ty = tid >> 4;

    float acc[4][4];
    #pragma unroll
    for (int i = 0; i < 4; i++)
        #pragma unroll
        for (int j = 0; j < 4; j++) acc[i][j] = 0.0f;

    const int lr = tid >> 2;           // 0..63
    const int lk = (tid & 3) * 4;      // 0,4,8,12

    for (int k0 = 0; k0 < K; k0 += BK) {
        const float* aptr = (k0 < 64)
            ? (A0 + (size_t)(bm + lr) * ldA0 + k0 + lk)
            : (A1 + (size_t)(bm + lr) * ldA1 + (k0 - 64) + lk);
        float4 va = __ldg((const float4*)aptr);
        float4 vb = __ldg((const float4*)(W + (size_t)(bn + lr) * K + k0 + lk));
        As[lr][lk] = va.x; As[lr][lk + 1] = va.y; As[lr][lk + 2] = va.z; As[lr][lk + 3] = va.w;
        Bs[lr][lk] = vb.x; Bs[lr][lk + 1] = vb.y; Bs[lr][lk + 2] = vb.z; Bs[lr][lk + 3] = vb.w;
        __syncthreads();

        #pragma unroll
        for (int k = 0; k < BK; k++) {
            float av[4], bv[4];
            #pragma unroll
            for (int i = 0; i < 4; i++) av[i] = As[ty * 4 + i][k];
            #pragma unroll
            for (int j = 0; j < 4; j++) bv[j] = Bs[tx * 4 + j][k];
            #pragma unroll
            for (int i = 0; i < 4; i++)
                #pragma unroll
                for (int j = 0; j < 4; j++)
                    acc[i][j] += av[i] * bv[j];
        }
        __syncthreads();
    }

    #pragma unroll
    for (int i = 0; i < 4; i++) {
        float4 o;
        o.x = acc[i][0] + (bias ? bias[bn + tx * 4 + 0] : 0.0f);
        o.y = acc[i][1] + (bias ? bias[bn + tx * 4 + 1] : 0.0f);
        o.z = acc[i][2] + (bias ? bias[bn + tx * 4 + 2] : 0.0f);
        o.w = acc[i][3] + (bias ? bias[bn + tx * 4 + 3] : 0.0f);
        *(float4*)(C + (size_t)(bm + ty * 4 + i) * ldC + bn + tx * 4) = o;
    }
}

// ---------------------------------------------------------------------------
// Scatter: one block per env, 128 threads. Reads xw, edges; writes gcn_out.
// Thread owns (agent a = tid>>3, 8 cols jb = (tid&7)*8).
// ---------------------------------------------------------------------------
__global__ __launch_bounds__(128)
void scatter_kernel(const float* __restrict__ xw,
                    const int* __restrict__ ei,
                    const float* __restrict__ bg,
                    float* __restrict__ gcn)
{
    const int env = blockIdx.x;
    const int tid = threadIdx.x;

    __shared__ float sxw[NUM_AGENTS][68];
    __shared__ float sdeg[NUM_AGENTS];
    __shared__ float snorm[E_PER_G];
    __shared__ int   srow[E_PER_G];
    __shared__ int   scol[E_PER_G];

    {   // xw env tile: 16x64 = 256 float4; 2 per thread
        const float4* xg = (const float4*)(xw + (size_t)env * NUM_AGENTS * GCN_H);
        #pragma unroll
        for (int t = 0; t < 2; t++) {
            int i = tid + t * 128;
            int a = i >> 4, q = i & 15;
            *(float4*)&sxw[a][q * 4] = __ldg(&xg[i]);
        }
        const int* eg = ei + (size_t)env * 2 * E_PER_G;
        srow[tid] = eg[tid] & 15;
        scol[tid] = eg[E_PER_G + tid] & 15;
        if (tid < NUM_AGENTS) sdeg[tid] = 1.0f;
    }
    __syncthreads();

    atomicAdd(&sdeg[scol[tid]], 1.0f);
    __syncthreads();

    snorm[tid] = rsqrtf(sdeg[srow[tid]] * sdeg[scol[tid]]);
    __syncthreads();

    const int a  = tid >> 3;
    const int jb = (tid & 7) * 8;

    float gacc[8];
    #pragma unroll
    for (int j = 0; j < 8; j++) gacc[j] = 0.0f;
    for (int e = 0; e < E_PER_G; e++) {
        if (scol[e] == a) {
            float nm = snorm[e];
            const float* src = &sxw[srow[e]][jb];
            float4 s0 = *(const float4*)src;
            float4 s1 = *(const float4*)(src + 4);
            gacc[0] += nm * s0.x;  gacc[1] += nm * s0.y;
            gacc[2] += nm * s0.z;  gacc[3] += nm * s0.w;
            gacc[4] += nm * s1.x;  gacc[5] += nm * s1.y;
            gacc[6] += nm * s1.z;  gacc[7] += nm * s1.w;
        }
    }
    const float invd = 1.0f / sdeg[a];
    float* dst = gcn + (size_t)env * NUM_AGENTS * GCN_H + a * GCN_H + jb;
    #pragma unroll
    for (int j = 0; j < 8; j++)
        dst[j] = gacc[j] + sxw[a][jb + j] * invd + __ldg(&bg[jb + j]);
}

// ---------------------------------------------------------------------------
// Gates: elementwise GRU update. G layout per row: [r-sum | z-sum | nx | nh].
// ---------------------------------------------------------------------------
__global__ __launch_bounds__(256)
void gates_kernel(const float* __restrict__ ph, float* __restrict__ hdst)
{
    const size_t idx = (size_t)blockIdx.x * 256 + threadIdx.x;  // node*64 range
    const size_t row = idx >> 6;
    const int    c   = (int)(idx & 63);
    const float* g   = g_G + row * 256;

    float r = 1.0f / (1.0f + expf(-g[c]));
    float z = 1.0f / (1.0f + expf(-g[64 + c]));
    float n = tanhf(g[128 + c] + r * g[192 + c]);
    float hp = ph[row * 64 + c];
    hdst[row * 64 + c] = (1.0f - z) * n + z * hp;
}

// ---------------------------------------------------------------------------
extern "C" void kernel_launch(void* const* d_in, const int* in_sizes, int n_in,
                              void* d_out, int out_size)
{
    const float* x    = (const float*)d_in[0];
    const int*   ei   = (const int*)d_in[1];      // int32 (JAX x64 disabled)
    const float* ph   = (const float*)d_in[2];
    const float* Wg   = (const float*)d_in[3];
    const float* bg   = (const float*)d_in[4];
    const float* Wih  = (const float*)d_in[5];
    const float* Whh  = (const float*)d_in[6];
    const float* bih  = (const float*)d_in[7];
    const float* bhh  = (const float*)d_in[8];
    const float* Wlin = (const float*)d_in[9];
    const float* blin = (const float*)d_in[10];

    float* out    = (float*)d_out;
    float* logits = out;                                  // [16384, 512]

    // Resolve device-scratch addresses (graph-capturable: host-side cached
    // lookups only — cudaGetSymbolAddress is not a stream op; do it inline).
    static float *p_xw = nullptr, *p_gcn = nullptr, *p_G = nullptr,
                 *p_h = nullptr, *p_WgT = nullptr, *p_B2 = nullptr,
                 *p_b2 = nullptr;
    if (!p_xw) {
        cudaGetSymbolAddress((void**)&p_xw,  g_xw);
        cudaGetSymbolAddress((void**)&p_gcn, g_gcn);
        cudaGetSymbolAddress((void**)&p_G,   g_G);
        cudaGetSymbolAddress((void**)&p_h,   g_h);
        cudaGetSymbolAddress((void**)&p_WgT, g_WgT);
        cudaGetSymbolAddress((void**)&p_B2,  g_B2);
        cudaGetSymbolAddress((void**)&p_b2,  g_bias2);
    }

    const long long need = (long long)NUM_ENVS * (OUT_DIM + FLAT_DIM);
    float* hout = ((long long)out_size >= need)
                      ? out + (size_t)NUM_ENVS * OUT_DIM
                      : p_h;

    // 0) prep fused weights
    prep_kernel<<<1, 256>>>(Wg, Wih, Whh, bih, bhh);

    // 1) xw = x_flat @ W_gcn   [262144,128] @ [128,64]  (no bias here!)
    {
        dim3 g(N_NODES / BM, GCN_H / BN);
        gemm_kernel<<<g, 256>>>(x, IN_DIM, x + 64, IN_DIM,
                                p_WgT, IN_DIM, nullptr, p_xw, GCN_H);
    }

    // 2) graph scatter -> gcn_out (adds self-loop + bias)
    scatter_kernel<<<NUM_ENVS, 128>>>(p_xw, ei, bg, p_gcn);

    // 3) GRU pre-activations: [gcn | h] @ B2^T  -> G [262144, 256]
    {
        dim3 g(N_NODES / BM, 256 / BN);
        gemm_kernel<<<g, 256>>>(p_gcn, GCN_H, ph, RNN_H,
                                p_B2, 128, p_b2, p_G, 256);
    }

    // 4) gates -> h_new
    gates_kernel<<<(N_NODES * RNN_H) / 256, 256>>>(ph, hout);

    // 5) logits = h_flat @ W_lin^T + b_lin   [16384,1024] @ [1024,512]
    {
        dim3 g(NUM_ENVS / BM, OUT_DIM / BN);
        gemm_kernel<<<g, 256>>>(hout, FLAT_DIM, hout + 64, FLAT_DIM,
                                Wlin, FLAT_DIM, blin, logits, OUT_DIM);
    }
}

// round 4
// speedup vs baseline: 4.3747x; 1.0491x over previous
#include <cuda_runtime.h>
#include <cuda_bf16.h>
#include <math.h>

// Problem constants
#define NUM_ENVS   16384
#define NUM_AGENTS 16
#define IN_DIM     128
#define GCN_H      64
#define RNN_H      64
#define E_PER_G    128
#define OUT_DIM    512           // 16*4*8
#define FLAT_DIM   1024          // NUM_AGENTS * RNN_H
#define N_NODES    ((size_t)NUM_ENVS * NUM_AGENTS)   // 262144

typedef unsigned long long u64;

// ---- device scratch (static; no runtime allocation) -----------------------
__device__ float g_xw [N_NODES * GCN_H];       // 67 MB  x @ W_gcn
__device__ float g_gcn[N_NODES * GCN_H];       // 67 MB  gcn output
__device__ float g_h  [N_NODES * RNN_H];       // 67 MB  h_new (if not in d_out)
__device__ float g_WgT [GCN_H * IN_DIM];       // [64][128]  W_gcn transposed
__device__ float g_B2  [256 * 128];            // fused GRU weights [256][128]
__device__ float g_bias2[256];

#define FFMA2(acc, a, b) \
    asm("fma.rn.f32x2 %0, %1, %2, %0;" : "+l"(acc) : "l"(a), "l"(b))

__device__ __forceinline__ float lo32(u64 v) { return __uint_as_float((unsigned)v); }
__device__ __forceinline__ float hi32(u64 v) { return __uint_as_float((unsigned)(v >> 32)); }

// ---------------------------------------------------------------------------
// Prep: transpose W_gcn, build fused GRU weight matrix B2 + bias2.
// B2 row n, col k over concatenated input [gcn(64) | h(64)]:
//   n in [0,128)  : r/z rows  -> Wih | Whh , bias = bih+bhh
//   n in [128,192): n_x rows  -> Wih | 0
//   n in [192,256): n_h rows  -> 0   | Whh
// ---------------------------------------------------------------------------
__global__ void prep_kernel(const float* __restrict__ Wg,
                            const float* __restrict__ Wih,
                            const float* __restrict__ Whh,
                            const float* __restrict__ bih,
                            const float* __restrict__ bhh)
{
    const int n = threadIdx.x;   // 0..255
    if (n < GCN_H) {
        for (int k = 0; k < IN_DIM; k++)
            g_WgT[n * IN_DIM + k] = Wg[k * GCN_H + n];
    }
    if (n < 128) {
        for (int k = 0; k < 64;  k++) g_B2[n * 128 + k]      = Wih[n * 64 + k];
        for (int k = 0; k < 64;  k++) g_B2[n * 128 + 64 + k] = Whh[n * 64 + k];
        g_bias2[n] = bih[n] + bhh[n];
    } else if (n < 192) {
        for (int k = 0; k < 64;  k++) g_B2[n * 128 + k]      = Wih[n * 64 + k];
        for (int k = 0; k < 64;  k++) g_B2[n * 128 + 64 + k] = 0.0f;
        g_bias2[n] = bih[n];
    } else {
        const int m = n - 64;    // Whh row 128..191
        for (int k = 0; k < 64;  k++) g_B2[n * 128 + k]      = 0.0f;
        for (int k = 0; k < 64;  k++) g_B2[n * 128 + 64 + k] = Whh[m * 64 + k];
        g_bias2[n] = bhh[m];
    }
}

// ---------------------------------------------------------------------------
// Generic packed-f32x2 GEMM: C[M,N] = [A0|A1] @ W^T + bias
// BM=128, BN=64, BK=16, 256 threads. Microtile 8Mx4N, row-paired f32x2.
// A split at k=64 (pass A1=A0+64, ldA1=ldA0 for an unsplit matrix).
// ---------------------------------------------------------------------------
#define GBM 128
#define GBN 64
#define GBK 16

__global__ __launch_bounds__(256)
void gemm_f32x2_kernel(const float* __restrict__ A0, int ldA0,
                       const float* __restrict__ A1, int ldA1,
                       const float* __restrict__ W,  int K,
                       const float* __restrict__ bias,
                       float* __restrict__ C, int ldC)
{
    __shared__ float As [GBK][GBM + 4];       // transposed A, stride 132
    __shared__ float Bsd[GBK][2 * GBN + 4];   // duplicated B,  stride 132

    const int tid = threadIdx.x;
    const int bm = blockIdx.x * GBM;
    const int bn = blockIdx.y * GBN;
    const int tx = tid & 15;          // 4 contiguous cols: tx*4..+3
    const int ty = tid >> 4;          // 8 rows: ty*8..+7 (4 pairs)
    const int lr = tid >> 2;          // 0..63 load row
    const int lk = (tid & 3) * 4;     // 0,4,8,12

    u64 acc[4][4];
    #pragma unroll
    for (int i = 0; i < 4; i++)
        #pragma unroll
        for (int j = 0; j < 4; j++) acc[i][j] = 0ull;

    for (int k0 = 0; k0 < K; k0 += GBK) {
        #pragma unroll
        for (int t = 0; t < 2; t++) {
            int row = lr + t * 64;
            const float* ap = (k0 < 64)
                ? (A0 + (size_t)(bm + row) * ldA0 + k0 + lk)
                : (A1 + (size_t)(bm + row) * ldA1 + (k0 - 64) + lk);
            float4 v = __ldg((const float4*)ap);
            As[lk + 0][row] = v.x; As[lk + 1][row] = v.y;
            As[lk + 2][row] = v.z; As[lk + 3][row] = v.w;
        }
        {
            float4 v = __ldg((const float4*)(W + (size_t)(bn + lr) * K + k0 + lk));
            Bsd[lk + 0][2 * lr] = v.x; Bsd[lk + 0][2 * lr + 1] = v.x;
            Bsd[lk + 1][2 * lr] = v.y; Bsd[lk + 1][2 * lr + 1] = v.y;
            Bsd[lk + 2][2 * lr] = v.z; Bsd[lk + 2][2 * lr + 1] = v.z;
            Bsd[lk + 3][2 * lr] = v.w; Bsd[lk + 3][2 * lr + 1] = v.w;
        }
        __syncthreads();

        #pragma unroll
        for (int k = 0; k < GBK; k++) {
            u64 av[4], bv[4];
            #pragma unroll
            for (int i = 0; i < 4; i++)
                av[i] = *(const u64*)&As[k][ty * 8 + 2 * i];
            #pragma unroll
            for (int j = 0; j < 4; j++)
                bv[j] = *(const u64*)&Bsd[k][(tx * 4 + j) * 2];
            #pragma unroll
            for (int i = 0; i < 4; i++)
                #pragma unroll
                for (int j = 0; j < 4; j++)
                    FFMA2(acc[i][j], av[i], bv[j]);
        }
        __syncthreads();
    }

    float bb[4];
    #pragma unroll
    for (int j = 0; j < 4; j++)
        bb[j] = bias ? __ldg(&bias[bn + tx * 4 + j]) : 0.0f;

    #pragma unroll
    for (int i = 0; i < 4; i++) {
        float4 o0, o1;
        o0.x = lo32(acc[i][0]) + bb[0];  o1.x = hi32(acc[i][0]) + bb[0];
        o0.y = lo32(acc[i][1]) + bb[1];  o1.y = hi32(acc[i][1]) + bb[1];
        o0.z = lo32(acc[i][2]) + bb[2];  o1.z = hi32(acc[i][2]) + bb[2];
        o0.w = lo32(acc[i][3]) + bb[3];  o1.w = hi32(acc[i][3]) + bb[3];
        size_t r0 = (size_t)(bm + ty * 8 + 2 * i);
        *(float4*)(C + r0 * ldC + bn + tx * 4)       = o0;
        *(float4*)(C + (r0 + 1) * ldC + bn + tx * 4) = o1;
    }
}

// ---------------------------------------------------------------------------
// GRU GEMM + fused gates: per 64-node tile computes all 256 gate
// pre-activations and folds them into h_new in registers.
// BM=64, BN=256, BK=16, 256 threads. Col mapping c = tx + 32j so each
// thread owns complete gate groups (j,j+2,j+4,j+6) for c=tx and c=tx+32.
// ---------------------------------------------------------------------------
#define RBK 16

__global__ __launch_bounds__(256)
void gru_fused_kernel(const float* __restrict__ gcn,
                      const float* __restrict__ ph,
                      float* __restrict__ hout)
{
    __shared__ float As [RBK][64 + 4];        // stride 68
    __shared__ float Bsd[RBK][512 + 4];       // duplicated B2, stride 516

    const int tid = threadIdx.x;
    const int bm = blockIdx.x * 64;           // node-row base
    const int tx = tid & 31;                  // cols tx + 32j
    const int ty = tid >> 5;                  // rows ty*8..+7 (4 pairs)
    const int lr = tid >> 2;                  // 0..63
    const int lk = (tid & 3) * 4;

    u64 acc[4][8];
    #pragma unroll
    for (int i = 0; i < 4; i++)
        #pragma unroll
        for (int j = 0; j < 8; j++) acc[i][j] = 0ull;

    for (int k0 = 0; k0 < 128; k0 += RBK) {
        {   // A tile: [gcn | ph] rows bm..bm+63
            const float* ap = (k0 < 64)
                ? (gcn + (size_t)(bm + lr) * 64 + k0 + lk)
                : (ph  + (size_t)(bm + lr) * 64 + (k0 - 64) + lk);
            float4 v = __ldg((const float4*)ap);
            As[lk + 0][lr] = v.x; As[lk + 1][lr] = v.y;
            As[lk + 2][lr] = v.z; As[lk + 3][lr] = v.w;
        }
        #pragma unroll
        for (int t = 0; t < 4; t++) {   // B2 rows lr + 64t
            int n = lr + t * 64;
            float4 v = *(const float4*)(g_B2 + (size_t)n * 128 + k0 + lk);
            Bsd[lk + 0][2 * n] = v.x; Bsd[lk + 0][2 * n + 1] = v.x;
            Bsd[lk + 1][2 * n] = v.y; Bsd[lk + 1][2 * n + 1] = v.y;
            Bsd[lk + 2][2 * n] = v.z; Bsd[lk + 2][2 * n + 1] = v.z;
            Bsd[lk + 3][2 * n] = v.w; Bsd[lk + 3][2 * n + 1] = v.w;
        }
        __syncthreads();

        #pragma unroll
        for (int k = 0; k < RBK; k++) {
            u64 av[4], bv[8];
            #pragma unroll
            for (int i = 0; i < 4; i++)
                av[i] = *(const u64*)&As[k][ty * 8 + 2 * i];
            #pragma unroll
            for (int j = 0; j < 8; j++)
                bv[j] = *(const u64*)&Bsd[k][2 * tx + 64 * j];
            #pragma unroll
            for (int i = 0; i < 4; i++)
                #pragma unroll
                for (int j = 0; j < 8; j++)
                    FFMA2(acc[i][j], av[i], bv[j]);
        }
        __syncthreads();
    }

    // Fused gate epilogue: thread owns cols {tx, tx+32}, rows ty*8..+7.
    #pragma unroll
    for (int half = 0; half < 2; half++) {
        const int c  = tx + 32 * half;            // 0..63
        const int j0 = half;                      // gate group j0, j0+2, j0+4, j0+6
        const float br = __ldg(&g_bias2[c]);
        const float bz = __ldg(&g_bias2[64 + c]);
        const float bx = __ldg(&g_bias2[128 + c]);
        const float bh = __ldg(&g_bias2[192 + c]);
        #pragma unroll
        for (int i = 0; i < 4; i++) {
            #pragma unroll
            for (int d = 0; d < 2; d++) {
                const size_t node = (size_t)bm + ty * 8 + 2 * i + d;
                float rp = (d ? hi32(acc[i][j0 + 0]) : lo32(acc[i][j0 + 0])) + br;
                float zp = (d ? hi32(acc[i][j0 + 2]) : lo32(acc[i][j0 + 2])) + bz;
                float nx = (d ? hi32(acc[i][j0 + 4]) : lo32(acc[i][j0 + 4])) + bx;
                float nh = (d ? hi32(acc[i][j0 + 6]) : lo32(acc[i][j0 + 6])) + bh;
                float r = 1.0f / (1.0f + expf(-rp));
                float z = 1.0f / (1.0f + expf(-zp));
                float n = tanhf(nx + r * nh);
                float hp = __ldg(&ph[node * 64 + c]);
                hout[node * 64 + c] = (1.0f - z) * n + z * hp;
            }
        }
    }
}

// ---------------------------------------------------------------------------
// Scatter: one block per env, 128 threads. Reads xw, edges; writes gcn_out.
// ---------------------------------------------------------------------------
__global__ __launch_bounds__(128)
void scatter_kernel(const float* __restrict__ xw,
                    const int* __restrict__ ei,
                    const float* __restrict__ bg,
                    float* __restrict__ gcn)
{
    const int env = blockIdx.x;
    const int tid = threadIdx.x;

    __shared__ float sxw[NUM_AGENTS][68];
    __shared__ float sdeg[NUM_AGENTS];
    __shared__ float snorm[E_PER_G];
    __shared__ int   srow[E_PER_G];
    __shared__ int   scol[E_PER_G];

    {
        const float4* xg = (const float4*)(xw + (size_t)env * NUM_AGENTS * GCN_H);
        #pragma unroll
        for (int t = 0; t < 2; t++) {
            int i = tid + t * 128;
            int a = i >> 4, q = i & 15;
            *(float4*)&sxw[a][q * 4] = __ldg(&xg[i]);
        }
        const int* eg = ei + (size_t)env * 2 * E_PER_G;
        srow[tid] = eg[tid] & 15;
        scol[tid] = eg[E_PER_G + tid] & 15;
        if (tid < NUM_AGENTS) sdeg[tid] = 1.0f;
    }
    __syncthreads();

    atomicAdd(&sdeg[scol[tid]], 1.0f);
    __syncthreads();

    snorm[tid] = rsqrtf(sdeg[srow[tid]] * sdeg[scol[tid]]);
    __syncthreads();

    const int a  = tid >> 3;
    const int jb = (tid & 7) * 8;

    float gacc[8];
    #pragma unroll
    for (int j = 0; j < 8; j++) gacc[j] = 0.0f;
    for (int e = 0; e < E_PER_G; e++) {
        if (scol[e] == a) {
            float nm = snorm[e];
            const float* src = &sxw[srow[e]][jb];
            float4 s0 = *(const float4*)src;
            float4 s1 = *(const float4*)(src + 4);
            gacc[0] += nm * s0.x;  gacc[1] += nm * s0.y;
            gacc[2] += nm * s0.z;  gacc[3] += nm * s0.w;
            gacc[4] += nm * s1.x;  gacc[5] += nm * s1.y;
            gacc[6] += nm * s1.z;  gacc[7] += nm * s1.w;
        }
    }
    const float invd = 1.0f / sdeg[a];
    float* dst = gcn + (size_t)env * NUM_AGENTS * GCN_H + a * GCN_H + jb;
    #pragma unroll
    for (int j = 0; j < 8; j++)
        dst[j] = gacc[j] + sxw[a][jb + j] * invd + __ldg(&bg[jb + j]);
}

// ---------------------------------------------------------------------------
extern "C" void kernel_launch(void* const* d_in, const int* in_sizes, int n_in,
                              void* d_out, int out_size)
{
    const float* x    = (const float*)d_in[0];
    const int*   ei   = (const int*)d_in[1];      // int32 (JAX x64 disabled)
    const float* ph   = (const float*)d_in[2];
    const float* Wg   = (const float*)d_in[3];
    const float* bg   = (const float*)d_in[4];
    const float* Wih  = (const float*)d_in[5];
    const float* Whh  = (const float*)d_in[6];
    const float* bih  = (const float*)d_in[7];
    const float* bhh  = (const float*)d_in[8];
    const float* Wlin = (const float*)d_in[9];
    const float* blin = (const float*)d_in[10];

    float* out    = (float*)d_out;
    float* logits = out;                                  // [16384, 512]

    static float *p_xw = nullptr, *p_gcn = nullptr, *p_h = nullptr,
                 *p_WgT = nullptr;
    if (!p_xw) {
        cudaGetSymbolAddress((void**)&p_xw,  g_xw);
        cudaGetSymbolAddress((void**)&p_gcn, g_gcn);
        cudaGetSymbolAddress((void**)&p_h,   g_h);
        cudaGetSymbolAddress((void**)&p_WgT, g_WgT);
    }

    const long long need = (long long)NUM_ENVS * (OUT_DIM + FLAT_DIM);
    float* hout = ((long long)out_size >= need)
                      ? out + (size_t)NUM_ENVS * OUT_DIM
                      : p_h;

    // 0) prep fused weights
    prep_kernel<<<1, 256>>>(Wg, Wih, Whh, bih, bhh);

    // 1) xw = x_flat @ W_gcn   [262144,128] @ [128,64]  (no bias here)
    {
        dim3 g(N_NODES / GBM, GCN_H / GBN);
        gemm_f32x2_kernel<<<g, 256>>>(x, IN_DIM, x + 64, IN_DIM,
                                      p_WgT, IN_DIM, nullptr, p_xw, GCN_H);
    }

    // 2) graph scatter -> gcn_out (adds self-loop + bias)
    scatter_kernel<<<NUM_ENVS, 128>>>(p_xw, ei, bg, p_gcn);

    // 3+4) GRU GEMM + gates fused -> h_new
    gru_fused_kernel<<<N_NODES / 64, 256>>>(p_gcn, ph, hout);

    // 5) logits = h_flat @ W_lin^T + b_lin   [16384,1024] @ [1024,512]
    {
        dim3 g(NUM_ENVS / GBM, OUT_DIM / GBN);
        gemm_f32x2_kernel<<<g, 256>>>(hout, FLAT_DIM, hout + 64, FLAT_DIM,
                                      Wlin, FLAT_DIM, blin, logits, OUT_DIM);
    }
}

// round 5
// speedup vs baseline: 6.4901x; 1.4836x over previous
#include <cuda_runtime.h>
#include <cuda_bf16.h>
#include <math.h>

// Problem constants
#define NUM_ENVS   16384
#define NUM_AGENTS 16
#define IN_DIM     128
#define GCN_H      64
#define RNN_H      64
#define E_PER_G    128
#define OUT_DIM    512
#define FLAT_DIM   1024
#define N_NODES    ((size_t)NUM_ENVS * NUM_AGENTS)   // 262144

typedef unsigned long long u64;

// ---- device scratch (static) ----------------------------------------------
__device__ float g_xw  [N_NODES * GCN_H];      // x @ W_gcn
__device__ float g_gcn [N_NODES * GCN_H];      // gcn output
__device__ float g_h   [N_NODES * RNN_H];      // h_new fallback
__device__ float g_B2T [128 * 256];            // fused GRU weights, k-major
__device__ float g_bias2[256];
__device__ float g_WlinT[1024 * 512];          // W_lin transposed, k-major

#define FFMA2(acc, a, b) \
    asm("fma.rn.f32x2 %0, %1, %2, %0;" : "+l"(acc) : "l"(a), "l"(b))

__device__ __forceinline__ float lo32(u64 v) { return __uint_as_float((unsigned)v); }
__device__ __forceinline__ float hi32(u64 v) { return __uint_as_float((unsigned)(v >> 32)); }
__device__ __forceinline__ u64 pack2(float v) {
    u64 r; asm("mov.b64 %0, {%1, %1};" : "=l"(r) : "f"(v)); return r;
}

// ---------------------------------------------------------------------------
// Prep: build fused GRU weight matrix B2 (k-major [128][256]) + bias2.
// Output col n: n<64 r, 64..127 z, 128..191 n_x, 192..255 n_h.
// Input k: k<64 = gcn part, k>=64 = h part.
// ---------------------------------------------------------------------------
__global__ void prep_kernel(const float* __restrict__ Wih,
                            const float* __restrict__ Whh,
                            const float* __restrict__ bih,
                            const float* __restrict__ bhh)
{
    const int n = threadIdx.x;   // 0..255
    for (int k = 0; k < 64; k++)
        g_B2T[k * 256 + n] = (n < 192) ? Wih[n * 64 + k] : 0.0f;
    for (int kk = 0; kk < 64; kk++) {
        float v;
        if      (n < 128) v = Whh[n * 64 + kk];
        else if (n < 192) v = 0.0f;
        else              v = Whh[(n - 64) * 64 + kk];
        g_B2T[(64 + kk) * 256 + n] = v;
    }
    if (n < 128)      g_bias2[n] = bih[n] + bhh[n];
    else if (n < 192) g_bias2[n] = bih[n];
    else              g_bias2[n] = bhh[n - 64];
}

// Transpose W_lin [512][1024] -> g_WlinT [1024][512] (k-major)
__global__ void transpose_wlin_kernel(const float* __restrict__ Wlin)
{
    const int idx = blockIdx.x * 256 + threadIdx.x;   // k*512 + n
    const int k = idx >> 9;
    const int n = idx & 511;
    g_WlinT[idx] = Wlin[n * 1024 + k];
}

// ---------------------------------------------------------------------------
// Generic GEMM: C[M,N] = A @ Wk + bias.  Wk is K-MAJOR [K][Nw] (ldW = Nw).
// BM=128, BN=64, BK=16, 128 threads (4 warps).
// Warp w: rows w*32..+31; ly=lane>>4 picks 16-row half (2 addrs/warp -> 1 phase).
// Thread: 8 row-pairs (f32x2 over M) x 4 cols (lx*4+j, lx=lane&15).
// ---------------------------------------------------------------------------
#define GBM 128
#define GBN 64
#define GBK 16

__global__ __launch_bounds__(128)
void gemm_f32x2_kernel(const float* __restrict__ A, int lda,
                       const float* __restrict__ Wk, int ldW, int K,
                       const float* __restrict__ bias,
                       float* __restrict__ C, int ldC)
{
    __shared__ float As [GBK][GBM + 4];   // transposed A, stride 132
    __shared__ float Bkn[GBK][GBN + 4];   // k-major B,    stride 68

    const int tid = threadIdx.x;
    const int bm = blockIdx.x * GBM;
    const int bn = blockIdx.y * GBN;
    const int w    = tid >> 5;
    const int lane = tid & 31;
    const int ly = lane >> 4;
    const int lx = lane & 15;
    const int rbase = w * 32 + ly * 16;

    u64 acc[8][4];
    #pragma unroll
    for (int i = 0; i < 8; i++)
        #pragma unroll
        for (int j = 0; j < 4; j++) acc[i][j] = 0ull;

    for (int k0 = 0; k0 < K; k0 += GBK) {
        {   // A tile: 128 rows x 16 k; 4 float4 per thread
            const int lr = tid >> 2;
            const int lk = (tid & 3) * 4;
            #pragma unroll
            for (int t = 0; t < 4; t++) {
                int row = lr + 32 * t;
                float4 v = __ldg((const float4*)(A + (size_t)(bm + row) * lda + k0 + lk));
                As[lk + 0][row] = v.x; As[lk + 1][row] = v.y;
                As[lk + 2][row] = v.z; As[lk + 3][row] = v.w;
            }
        }
        {   // B tile: 16 k x 64 n, straight float4 copies (2/thread)
            #pragma unroll
            for (int t = 0; t < 2; t++) {
                int idx = tid * 2 + t;          // 0..255
                int k = idx >> 4;
                int n4 = (idx & 15) * 4;
                float4 v = __ldg((const float4*)(Wk + (size_t)(k0 + k) * ldW + bn + n4));
                *(float4*)&Bkn[k][n4] = v;
            }
        }
        __syncthreads();

        #pragma unroll
        for (int k = 0; k < GBK; k++) {
            u64 av[8], bv[4];
            #pragma unroll
            for (int i = 0; i < 8; i++)
                av[i] = *(const u64*)&As[k][rbase + 2 * i];
            #pragma unroll
            for (int j = 0; j < 4; j++)
                bv[j] = pack2(Bkn[k][lx * 4 + j]);
            #pragma unroll
            for (int i = 0; i < 8; i++)
                #pragma unroll
                for (int j = 0; j < 4; j++)
                    FFMA2(acc[i][j], av[i], bv[j]);
        }
        __syncthreads();
    }

    float bb[4];
    #pragma unroll
    for (int j = 0; j < 4; j++)
        bb[j] = bias ? __ldg(&bias[bn + lx * 4 + j]) : 0.0f;

    #pragma unroll
    for (int i = 0; i < 8; i++) {
        float4 o0, o1;
        o0.x = lo32(acc[i][0]) + bb[0];  o1.x = hi32(acc[i][0]) + bb[0];
        o0.y = lo32(acc[i][1]) + bb[1];  o1.y = hi32(acc[i][1]) + bb[1];
        o0.z = lo32(acc[i][2]) + bb[2];  o1.z = hi32(acc[i][2]) + bb[2];
        o0.w = lo32(acc[i][3]) + bb[3];  o1.w = hi32(acc[i][3]) + bb[3];
        size_t r0 = (size_t)(bm + rbase + 2 * i);
        *(float4*)(C + r0 * ldC + bn + lx * 4)       = o0;
        *(float4*)(C + (r0 + 1) * ldC + bn + lx * 4) = o1;
    }
}

// ---------------------------------------------------------------------------
// GRU GEMM + fused gates. M-tile 64 nodes, N=256 gates, K=128 ([gcn|h]).
// 128 threads (4 warps). Warp w: rows w*16..+15 (av broadcast).
// Thread cols c = lane + 32j (gate-complete groups).
// ---------------------------------------------------------------------------
#define RBK 16

__global__ __launch_bounds__(128)
void gru_fused_kernel(const float* __restrict__ gcn,
                      const float* __restrict__ ph,
                      float* __restrict__ hout)
{
    __shared__ float As[RBK][64 + 4];     // stride 68
    __shared__ float Bs[RBK][256 + 4];    // stride 260

    const int tid = threadIdx.x;
    const int bm = blockIdx.x * 64;
    const int w    = tid >> 5;
    const int lane = tid & 31;
    const int rbase = w * 16;

    u64 acc[8][8];
    #pragma unroll
    for (int i = 0; i < 8; i++)
        #pragma unroll
        for (int j = 0; j < 8; j++) acc[i][j] = 0ull;

    for (int k0 = 0; k0 < 128; k0 += RBK) {
        {   // A tile: 64 rows x 16 k from [gcn | ph]
            const int lr = tid >> 1;
            const int lk = (tid & 1) * 8;
            const float* base = (k0 < 64) ? gcn : ph;
            const int koff = (k0 < 64) ? k0 : (k0 - 64);
            #pragma unroll
            for (int t = 0; t < 2; t++) {
                float4 v = __ldg((const float4*)(base + (size_t)(bm + lr) * 64 + koff + lk + 4 * t));
                As[lk + 4 * t + 0][lr] = v.x; As[lk + 4 * t + 1][lr] = v.y;
                As[lk + 4 * t + 2][lr] = v.z; As[lk + 4 * t + 3][lr] = v.w;
            }
        }
        {   // B tile: 16 k x 256 n (8 float4 per thread)
            #pragma unroll
            for (int t = 0; t < 8; t++) {
                int idx = tid + 128 * t;        // 0..1023
                int k = idx >> 6;
                int n4 = (idx & 63) * 4;
                float4 v = *(const float4*)(g_B2T + (size_t)(k0 + k) * 256 + n4);
                *(float4*)&Bs[k][n4] = v;
            }
        }
        __syncthreads();

        #pragma unroll
        for (int k = 0; k < RBK; k++) {
            u64 av[8], bv[8];
            #pragma unroll
            for (int i = 0; i < 8; i++)
                av[i] = *(const u64*)&As[k][rbase + 2 * i];
            #pragma unroll
            for (int j = 0; j < 8; j++)
                bv[j] = pack2(Bs[k][lane + 32 * j]);
            #pragma unroll
            for (int i = 0; i < 8; i++)
                #pragma unroll
                for (int j = 0; j < 8; j++)
                    FFMA2(acc[i][j], av[i], bv[j]);
        }
        __syncthreads();
    }

    #pragma unroll
    for (int half = 0; half < 2; half++) {
        const int c  = lane + 32 * half;
        const int j0 = half;
        const float br = __ldg(&g_bias2[c]);
        const float bz = __ldg(&g_bias2[64 + c]);
        const float bx = __ldg(&g_bias2[128 + c]);
        const float bh = __ldg(&g_bias2[192 + c]);
        #pragma unroll
        for (int i = 0; i < 8; i++) {
            #pragma unroll
            for (int d = 0; d < 2; d++) {
                const size_t node = (size_t)bm + rbase + 2 * i + d;
                float rp = (d ? hi32(acc[i][j0 + 0]) : lo32(acc[i][j0 + 0])) + br;
                float zp = (d ? hi32(acc[i][j0 + 2]) : lo32(acc[i][j0 + 2])) + bz;
                float nx = (d ? hi32(acc[i][j0 + 4]) : lo32(acc[i][j0 + 4])) + bx;
                float nh = (d ? hi32(acc[i][j0 + 6]) : lo32(acc[i][j0 + 6])) + bh;
                float r = 1.0f / (1.0f + expf(-rp));
                float z = 1.0f / (1.0f + expf(-zp));
                float n = tanhf(nx + r * nh);
                float hp = __ldg(&ph[node * 64 + c]);
                hout[node * 64 + c] = (1.0f - z) * n + z * hp;
            }
        }
    }
}

// ---------------------------------------------------------------------------
// Scatter: one block per env, 128 threads.
// ---------------------------------------------------------------------------
__global__ __launch_bounds__(128)
void scatter_kernel(const float* __restrict__ xw,
                    const int* __restrict__ ei,
                    const float* __restrict__ bg,
                    float* __restrict__ gcn)
{
    const int env = blockIdx.x;
    const int tid = threadIdx.x;

    __shared__ float sxw[NUM_AGENTS][68];
    __shared__ float sdeg[NUM_AGENTS];
    __shared__ float snorm[E_PER_G];
    __shared__ int   srow[E_PER_G];
    __shared__ int   scol[E_PER_G];

    {
        const float4* xg = (const float4*)(xw + (size_t)env * NUM_AGENTS * GCN_H);
        #pragma unroll
        for (int t = 0; t < 2; t++) {
            int i = tid + t * 128;
            int a = i >> 4, q = i & 15;
            *(float4*)&sxw[a][q * 4] = __ldg(&xg[i]);
        }
        const int* eg = ei + (size_t)env * 2 * E_PER_G;
        srow[tid] = eg[tid] & 15;
        scol[tid] = eg[E_PER_G + tid] & 15;
        if (tid < NUM_AGENTS) sdeg[tid] = 1.0f;
    }
    __syncthreads();

    atomicAdd(&sdeg[scol[tid]], 1.0f);
    __syncthreads();

    snorm[tid] = rsqrtf(sdeg[srow[tid]] * sdeg[scol[tid]]);
    __syncthreads();

    const int a  = tid >> 3;
    const int jb = (tid & 7) * 8;

    float gacc[8];
    #pragma unroll
    for (int j = 0; j < 8; j++) gacc[j] = 0.0f;
    for (int e = 0; e < E_PER_G; e++) {
        if (scol[e] == a) {
            float nm = snorm[e];
            const float* src = &sxw[srow[e]][jb];
            float4 s0 = *(const float4*)src;
            float4 s1 = *(const float4*)(src + 4);
            gacc[0] += nm * s0.x;  gacc[1] += nm * s0.y;
            gacc[2] += nm * s0.z;  gacc[3] += nm * s0.w;
            gacc[4] += nm * s1.x;  gacc[5] += nm * s1.y;
            gacc[6] += nm * s1.z;  gacc[7] += nm * s1.w;
        }
    }
    const float invd = 1.0f / sdeg[a];
    float* dst = gcn + (size_t)env * NUM_AGENTS * GCN_H + a * GCN_H + jb;
    #pragma unroll
    for (int j = 0; j < 8; j++)
        dst[j] = gacc[j] + sxw[a][jb + j] * invd + __ldg(&bg[jb + j]);
}

// ---------------------------------------------------------------------------
extern "C" void kernel_launch(void* const* d_in, const int* in_sizes, int n_in,
                              void* d_out, int out_size)
{
    const float* x    = (const float*)d_in[0];
    const int*   ei   = (const int*)d_in[1];
    const float* ph   = (const float*)d_in[2];
    const float* Wg   = (const float*)d_in[3];     // [128][64] k-major already
    const float* bg   = (const float*)d_in[4];
    const float* Wih  = (const float*)d_in[5];
    const float* Whh  = (const float*)d_in[6];
    const float* bih  = (const float*)d_in[7];
    const float* bhh  = (const float*)d_in[8];
    const float* Wlin = (const float*)d_in[9];
    const float* blin = (const float*)d_in[10];

    float* out    = (float*)d_out;
    float* logits = out;

    static float *p_xw = nullptr, *p_gcn = nullptr, *p_h = nullptr,
                 *p_WlinT = nullptr;
    if (!p_xw) {
        cudaGetSymbolAddress((void**)&p_xw,    g_xw);
        cudaGetSymbolAddress((void**)&p_gcn,   g_gcn);
        cudaGetSymbolAddress((void**)&p_h,     g_h);
        cudaGetSymbolAddress((void**)&p_WlinT, g_WlinT);
    }

    const long long need = (long long)NUM_ENVS * (OUT_DIM + FLAT_DIM);
    float* hout = ((long long)out_size >= need)
                      ? out + (size_t)NUM_ENVS * OUT_DIM
                      : p_h;

    prep_kernel<<<1, 256>>>(Wih, Whh, bih, bhh);
    transpose_wlin_kernel<<<(1024 * 512) / 256, 256>>>(Wlin);

    // 1) xw = x @ W_gcn
    {
        dim3 g(N_NODES / GBM, 1);
        gemm_f32x2_kernel<<<g, 128>>>(x, IN_DIM, Wg, GCN_H, IN_DIM, nullptr,
                                      p_xw, GCN_H);
    }

    // 2) scatter
    scatter_kernel<<<NUM_ENVS, 128>>>(p_xw, ei, bg, p_gcn);

    // 3+4) GRU + gates
    gru_fused_kernel<<<N_NODES / 64, 128>>>(p_gcn, ph, hout);

    // 5) logits
    {
        dim3 g(NUM_ENVS / GBM, OUT_DIM / GBN);
        gemm_f32x2_kernel<<<g, 128>>>(hout, FLAT_DIM, p_WlinT, OUT_DIM,
                                      FLAT_DIM, blin, logits, OUT_DIM);
    }
}

// round 7
// speedup vs baseline: 7.2874x; 1.1228x over previous
#include <cuda_runtime.h>
#include <cuda_bf16.h>
#include <math.h>

// Problem constants
#define NUM_ENVS   16384
#define NUM_AGENTS 16
#define IN_DIM     128
#define GCN_H      64
#define RNN_H      64
#define E_PER_G    128
#define OUT_DIM    512
#define FLAT_DIM   1024
#define N_NODES    ((size_t)NUM_ENVS * NUM_AGENTS)   // 262144

typedef unsigned long long u64;

// ---- device scratch (static) ----------------------------------------------
__device__ float g_xw  [N_NODES * GCN_H];      // x @ W_gcn
__device__ float g_h   [N_NODES * RNN_H];      // h_new fallback
__device__ float g_B2T [128 * 256];            // fused GRU weights, k-major
__device__ float g_bias2[256];
__device__ float g_WlinT[1024 * 512];          // W_lin transposed, k-major

#define FFMA2(acc, a, b) \
    asm("fma.rn.f32x2 %0, %1, %2, %0;" : "+l"(acc) : "l"(a), "l"(b))

__device__ __forceinline__ float lo32(u64 v) { return __uint_as_float((unsigned)v); }
__device__ __forceinline__ float hi32(u64 v) { return __uint_as_float((unsigned)(v >> 32)); }
__device__ __forceinline__ u64 pack2(float v) {
    u64 r; asm("mov.b64 %0, {%1, %1};" : "=l"(r) : "f"(v)); return r;
}

// ---------------------------------------------------------------------------
// Prep: fused GRU weights B2 (k-major [128][256]) + bias2.
// cols: 0..63 r, 64..127 z, 128..191 n_x, 192..255 n_h.  k: [gcn(64)|h(64)].
// ---------------------------------------------------------------------------
__global__ void prep_kernel(const float* __restrict__ Wih,
                            const float* __restrict__ Whh,
                            const float* __restrict__ bih,
                            const float* __restrict__ bhh)
{
    const int n = threadIdx.x;   // 0..255
    for (int k = 0; k < 64; k++)
        g_B2T[k * 256 + n] = (n < 192) ? Wih[n * 64 + k] : 0.0f;
    for (int kk = 0; kk < 64; kk++) {
        float v;
        if      (n < 128) v = Whh[n * 64 + kk];
        else if (n < 192) v = 0.0f;
        else              v = Whh[(n - 64) * 64 + kk];
        g_B2T[(64 + kk) * 256 + n] = v;
    }
    if (n < 128)      g_bias2[n] = bih[n] + bhh[n];
    else if (n < 192) g_bias2[n] = bih[n];
    else              g_bias2[n] = bhh[n - 64];
}

__global__ void transpose_wlin_kernel(const float* __restrict__ Wlin)
{
    const int idx = blockIdx.x * 256 + threadIdx.x;   // k*512 + n
    const int k = idx >> 9;
    const int n = idx & 511;
    g_WlinT[idx] = Wlin[n * 1024 + k];
}

// ---------------------------------------------------------------------------
// Generic GEMM: C = A @ Wk + bias, Wk k-major [K][ldW].
// BM=128, BN=64, BK=32, 128 threads. 8 row-pairs x 4 cols per thread.
// ---------------------------------------------------------------------------
#define GBM 128
#define GBN 64
#define GBK 32

__global__ __launch_bounds__(128)
void gemm_f32x2_kernel(const float* __restrict__ A, int lda,
                       const float* __restrict__ Wk, int ldW, int K,
                       const float* __restrict__ bias,
                       float* __restrict__ C, int ldC)
{
    __shared__ float As [GBK][GBM + 4];   // stride 132
    __shared__ float Bkn[GBK][GBN + 4];   // stride 68

    const int tid = threadIdx.x;
    const int bm = blockIdx.x * GBM;
    const int bn = blockIdx.y * GBN;
    const int w    = tid >> 5;
    const int lane = tid & 31;
    const int ly = lane >> 4;
    const int lx = lane & 15;
    const int rbase = w * 32 + ly * 16;

    u64 acc[8][4];
    #pragma unroll
    for (int i = 0; i < 8; i++)
        #pragma unroll
        for (int j = 0; j < 4; j++) acc[i][j] = 0ull;

    const int lr = tid >> 2;
    const int lk = (tid & 3) * 4;

    for (int k0 = 0; k0 < K; k0 += GBK) {
        #pragma unroll
        for (int half = 0; half < 2; half++) {
            const int kb = k0 + half * 16;
            #pragma unroll
            for (int t = 0; t < 4; t++) {
                int row = lr + 32 * t;
                float4 v = __ldg((const float4*)(A + (size_t)(bm + row) * lda + kb + lk));
                As[half * 16 + lk + 0][row] = v.x;
                As[half * 16 + lk + 1][row] = v.y;
                As[half * 16 + lk + 2][row] = v.z;
                As[half * 16 + lk + 3][row] = v.w;
            }
            #pragma unroll
            for (int t = 0; t < 2; t++) {
                int idx = tid * 2 + t;
                int k = idx >> 4;
                int n4 = (idx & 15) * 4;
                float4 v = __ldg((const float4*)(Wk + (size_t)(kb + k) * ldW + bn + n4));
                *(float4*)&Bkn[half * 16 + k][n4] = v;
            }
        }
        __syncthreads();

        #pragma unroll
        for (int k = 0; k < GBK; k++) {
            u64 av[8], bv[4];
            #pragma unroll
            for (int i = 0; i < 8; i++)
                av[i] = *(const u64*)&As[k][rbase + 2 * i];
            #pragma unroll
            for (int j = 0; j < 4; j++)
                bv[j] = pack2(Bkn[k][lx * 4 + j]);
            #pragma unroll
            for (int i = 0; i < 8; i++)
                #pragma unroll
                for (int j = 0; j < 4; j++)
                    FFMA2(acc[i][j], av[i], bv[j]);
        }
        __syncthreads();
    }

    float bb[4];
    #pragma unroll
    for (int j = 0; j < 4; j++)
        bb[j] = bias ? __ldg(&bias[bn + lx * 4 + j]) : 0.0f;

    #pragma unroll
    for (int i = 0; i < 8; i++) {
        float4 o0, o1;
        o0.x = lo32(acc[i][0]) + bb[0];  o1.x = hi32(acc[i][0]) + bb[0];
        o0.y = lo32(acc[i][1]) + bb[1];  o1.y = hi32(acc[i][1]) + bb[1];
        o0.z = lo32(acc[i][2]) + bb[2];  o1.z = hi32(acc[i][2]) + bb[2];
        o0.w = lo32(acc[i][3]) + bb[3];  o1.w = hi32(acc[i][3]) + bb[3];
        size_t r0 = (size_t)(bm + rbase + 2 * i);
        *(float4*)(C + r0 * ldC + bn + lx * 4)       = o0;
        *(float4*)(C + (r0 + 1) * ldC + bn + lx * 4) = o1;
    }
}

// ---------------------------------------------------------------------------
// GRU mega-kernel: per block = 64 nodes = 4 whole envs, 128 threads.
//   1. build 4 normalized 16x16 adjacency matrices (smem atomics)
//   2. gcn = Adj @ xw + bias  -> persistent transposed A-tile sAg[k][row]
//   3. GEMM vs fused B2 (k<64: gates r,z,nx; k>=64: r,z,nh) + gate epilogue
// Shared memory is a manually-carved union (fits in 48KB static):
//   [0,16896)        sAg   float[64][66]   (persistent gcn^T)
//   [16896,37760)    region2: Bs float[16][260] (16640) + Ash float[16][66]
//                    -- aliased by sxw float[64][66] during adjacency phase
//   [37760,42112)    adj   float[4][16][17]
//   [42112,42368)    deg   float[64]
//   [42368,46464)    sed   int[4][256]
// ---------------------------------------------------------------------------
__global__ __launch_bounds__(128)
void gru_mega_kernel(const float* __restrict__ xw,
                     const int* __restrict__ ei,
                     const float* __restrict__ bg,
                     const float* __restrict__ ph,
                     float* __restrict__ hout)
{
    __shared__ __align__(16) char smem_raw[46464];
    float* sAg = (float*)smem_raw;                       // stride 66
    float* Bs  = (float*)(smem_raw + 16896);             // stride 260
    float* Ash = (float*)(smem_raw + 16896 + 16640);     // stride 66
    float* sxw = (float*)(smem_raw + 16896);             // stride 66 (alias)
    float* adj = (float*)(smem_raw + 37760);             // [(e*16+a)*17+b]
    float* deg = (float*)(smem_raw + 42112);
    int*   sed = (int*)  (smem_raw + 42368);             // [e*256 + pos]

    const int tid  = threadIdx.x;
    const int bm   = blockIdx.x * 64;                    // node base
    const int env0 = blockIdx.x * 4;
    const int w    = tid >> 5;
    const int lane = tid & 31;
    const int rbase = w * 16;

    // ---- load edges + stage xw^T + init ------------------------------------
    #pragma unroll
    for (int t = 0; t < 8; t++) {
        int idx = tid + 128 * t;                         // 0..1023
        sed[idx] = __ldg(&ei[(size_t)env0 * 2 * E_PER_G + idx]) & 15;
    }
    #pragma unroll
    for (int t = 0; t < 8; t++) {
        int idx = tid + 128 * t;                         // 0..1023
        int row = idx >> 4, q = idx & 15;
        float4 v = __ldg((const float4*)(xw + (size_t)(bm + row) * 64 + q * 4));
        sxw[(4 * q + 0) * 66 + row] = v.x;
        sxw[(4 * q + 1) * 66 + row] = v.y;
        sxw[(4 * q + 2) * 66 + row] = v.z;
        sxw[(4 * q + 3) * 66 + row] = v.w;
    }
    if (tid < 64) deg[tid] = 1.0f;                       // self-loop count
    #pragma unroll
    for (int t = 0; t < 9; t++) {
        int i = tid + 128 * t;
        if (i < 4 * 16 * 17) adj[i] = 0.0f;
    }
    __syncthreads();

    // ---- degrees -----------------------------------------------------------
    #pragma unroll
    for (int t = 0; t < 4; t++) {
        int eidx = tid + 128 * t;                        // 0..511
        int e = eidx >> 7, p = eidx & 127;
        atomicAdd(&deg[e * 16 + sed[e * 256 + 128 + p]], 1.0f);
    }
    __syncthreads();

    // ---- adjacency (normalized) + self-loop --------------------------------
    #pragma unroll
    for (int t = 0; t < 4; t++) {
        int eidx = tid + 128 * t;
        int e = eidx >> 7, p = eidx & 127;
        int row = sed[e * 256 + p];
        int col = sed[e * 256 + 128 + p];
        float nm = rsqrtf(deg[e * 16 + row] * deg[e * 16 + col]);
        atomicAdd(&adj[(e * 16 + col) * 17 + row], nm);
    }
    if (tid < 64) {
        int e = tid >> 4, a = tid & 15;
        atomicAdd(&adj[(e * 16 + a) * 17 + a], 1.0f / deg[tid]);
    }
    __syncthreads();

    // ---- gcn = Adj @ xw + bias  -> sAg[k][row] -----------------------------
    {
        const int a_loc = tid & 63;
        const int jh = tid >> 6;
        const int e = a_loc >> 4, a = a_loc & 15;
        float wrow[16];
        #pragma unroll
        for (int b = 0; b < 16; b++)
            wrow[b] = adj[(e * 16 + a) * 17 + b];
        #pragma unroll
        for (int jj = 0; jj < 32; jj++) {
            int j = jh * 32 + jj;
            float acc = __ldg(&bg[j]);
            #pragma unroll
            for (int b = 0; b < 16; b++)
                acc += wrow[b] * sxw[j * 66 + e * 16 + b];
            sAg[j * 66 + a_loc] = acc;
        }
    }
    __syncthreads();   // sxw dead; region2 free for Bs/Ash

    u64 acc[8][8];
    #pragma unroll
    for (int i = 0; i < 8; i++)
        #pragma unroll
        for (int j = 0; j < 8; j++) acc[i][j] = 0ull;

    // ---- phase 1: k in [0,64), A = sAg (resident), gates r,z,nx ------------
    for (int k0 = 0; k0 < 64; k0 += 16) {
        #pragma unroll
        for (int t = 0; t < 8; t++) {                    // stage Bs 16x256
            int idx = tid + 128 * t;
            int k = idx >> 6, n4 = (idx & 63) * 4;
            float4 v = *(const float4*)(g_B2T + (size_t)(k0 + k) * 256 + n4);
            *(float4*)&Bs[k * 260 + n4] = v;
        }
        __syncthreads();
        #pragma unroll
        for (int k = 0; k < 16; k++) {
            const float* ar = sAg + (k0 + k) * 66;
            u64 av[8];
            #pragma unroll
            for (int i = 0; i < 8; i++)
                av[i] = *(const u64*)&ar[rbase + 2 * i];
            #pragma unroll
            for (int g = 0; g < 6; g++) {
                u64 bv = pack2(Bs[k * 260 + lane + 32 * g]);
                #pragma unroll
                for (int i = 0; i < 8; i++)
                    FFMA2(acc[i][g], av[i], bv);
            }
        }
        __syncthreads();
    }

    // ---- phase 2: k in [64,128), A = ph (staged), gates r,z,nh -------------
    for (int k0 = 64; k0 < 128; k0 += 16) {
        {   // stage Ash 16x64 from ph
            const int lr = tid >> 1;
            const int lk = (tid & 1) * 8;
            #pragma unroll
            for (int t = 0; t < 2; t++) {
                float4 v = __ldg((const float4*)(ph + (size_t)(bm + lr) * 64 + (k0 - 64) + lk + 4 * t));
                Ash[(lk + 4 * t + 0) * 66 + lr] = v.x;
                Ash[(lk + 4 * t + 1) * 66 + lr] = v.y;
                Ash[(lk + 4 * t + 2) * 66 + lr] = v.z;
                Ash[(lk + 4 * t + 3) * 66 + lr] = v.w;
            }
        }
        #pragma unroll
        for (int t = 0; t < 8; t++) {                    // stage Bs
            int idx = tid + 128 * t;
            int k = idx >> 6, n4 = (idx & 63) * 4;
            float4 v = *(const float4*)(g_B2T + (size_t)(k0 + k) * 256 + n4);
            *(float4*)&Bs[k * 260 + n4] = v;
        }
        __syncthreads();
        #pragma unroll
        for (int k = 0; k < 16; k++) {
            const float* ar = Ash + k * 66;
            u64 av[8];
            #pragma unroll
            for (int i = 0; i < 8; i++)
                av[i] = *(const u64*)&ar[rbase + 2 * i];
            #pragma unroll
            for (int gg = 0; gg < 6; gg++) {
                const int g = (gg < 4) ? gg : (gg + 2);  // 0,1,2,3,6,7
                u64 bv = pack2(Bs[k * 260 + lane + 32 * g]);
                #pragma unroll
                for (int i = 0; i < 8; i++)
                    FFMA2(acc[i][g], av[i], bv);
            }
        }
        __syncthreads();
    }

    // ---- gate epilogue -----------------------------------------------------
    #pragma unroll
    for (int half = 0; half < 2; half++) {
        const int c  = lane + 32 * half;
        const int j0 = half;
        const float br = __ldg(&g_bias2[c]);
        const float bz = __ldg(&g_bias2[64 + c]);
        const float bx = __ldg(&g_bias2[128 + c]);
        const float bh = __ldg(&g_bias2[192 + c]);
        #pragma unroll
        for (int i = 0; i < 8; i++) {
            #pragma unroll
            for (int d = 0; d < 2; d++) {
                const size_t node = (size_t)bm + rbase + 2 * i + d;
                float rp = (d ? hi32(acc[i][j0 + 0]) : lo32(acc[i][j0 + 0])) + br;
                float zp = (d ? hi32(acc[i][j0 + 2]) : lo32(acc[i][j0 + 2])) + bz;
                float nx = (d ? hi32(acc[i][j0 + 4]) : lo32(acc[i][j0 + 4])) + bx;
                float nh = (d ? hi32(acc[i][j0 + 6]) : lo32(acc[i][j0 + 6])) + bh;
                float r = 1.0f / (1.0f + expf(-rp));
                float z = 1.0f / (1.0f + expf(-zp));
                float n = tanhf(nx + r * nh);
                float hp = __ldg(&ph[node * 64 + c]);
                hout[node * 64 + c] = (1.0f - z) * n + z * hp;
            }
        }
    }
}

// ---------------------------------------------------------------------------
extern "C" void kernel_launch(void* const* d_in, const int* in_sizes, int n_in,
                              void* d_out, int out_size)
{
    const float* x    = (const float*)d_in[0];
    const int*   ei   = (const int*)d_in[1];
    const float* ph   = (const float*)d_in[2];
    const float* Wg   = (const float*)d_in[3];     // [128][64] k-major
    const float* bg   = (const float*)d_in[4];
    const float* Wih  = (const float*)d_in[5];
    const float* Whh  = (const float*)d_in[6];
    const float* bih  = (const float*)d_in[7];
    const float* bhh  = (const float*)d_in[8];
    const float* Wlin = (const float*)d_in[9];
    const float* blin = (const float*)d_in[10];

    float* out    = (float*)d_out;
    float* logits = out;

    static float *p_xw = nullptr, *p_h = nullptr, *p_WlinT = nullptr;
    if (!p_xw) {
        cudaGetSymbolAddress((void**)&p_xw,    g_xw);
        cudaGetSymbolAddress((void**)&p_h,     g_h);
        cudaGetSymbolAddress((void**)&p_WlinT, g_WlinT);
    }

    const long long need = (long long)NUM_ENVS * (OUT_DIM + FLAT_DIM);
    float* hout = ((long long)out_size >= need)
                      ? out + (size_t)NUM_ENVS * OUT_DIM
                      : p_h;

    prep_kernel<<<1, 256>>>(Wih, Whh, bih, bhh);
    transpose_wlin_kernel<<<(1024 * 512) / 256, 256>>>(Wlin);

    // 1) xw = x @ W_gcn
    {
        dim3 g(N_NODES / GBM, 1);
        gemm_f32x2_kernel<<<g, 128>>>(x, IN_DIM, Wg, GCN_H, IN_DIM, nullptr,
                                      p_xw, GCN_H);
    }

    // 2+3+4) scatter + GRU + gates fused
    gru_mega_kernel<<<N_NODES / 64, 128>>>(p_xw, ei, bg, ph, hout);

    // 5) logits
    {
        dim3 g(NUM_ENVS / GBM, OUT_DIM / GBN);
        gemm_f32x2_kernel<<<g, 128>>>(hout, FLAT_DIM, p_WlinT, OUT_DIM,
                                      FLAT_DIM, blin, logits, OUT_DIM);
    }
}

// round 8
// speedup vs baseline: 8.0074x; 1.0988x over previous
#include <cuda_runtime.h>
#include <cuda_bf16.h>
#include <math.h>

// Problem constants
#define NUM_ENVS   16384
#define NUM_AGENTS 16
#define IN_DIM     128
#define GCN_H      64
#define RNN_H      64
#define E_PER_G    128
#define OUT_DIM    512
#define FLAT_DIM   1024
#define N_NODES    ((size_t)NUM_ENVS * NUM_AGENTS)   // 262144

typedef unsigned long long u64;

// ---- device scratch (static) ----------------------------------------------
__device__ float g_xw  [N_NODES * GCN_H];      // x @ W_gcn
__device__ float g_h   [N_NODES * RNN_H];      // h_new fallback
__device__ float g_B2T [128 * 256];            // fused GRU weights, k-major
__device__ float g_bias2[256];
__device__ float g_WlinT[1024 * 512];          // W_lin transposed, k-major

#define FFMA2(acc, a, b) \
    asm("fma.rn.f32x2 %0, %1, %2, %0;" : "+l"(acc) : "l"(a), "l"(b))

__device__ __forceinline__ float lo32(u64 v) { return __uint_as_float((unsigned)v); }
__device__ __forceinline__ float hi32(u64 v) { return __uint_as_float((unsigned)(v >> 32)); }
__device__ __forceinline__ u64 pack2(float v) {
    u64 r; asm("mov.b64 %0, {%1, %1};" : "=l"(r) : "f"(v)); return r;
}

// ---------------------------------------------------------------------------
// Prep: fused GRU weights B2 (k-major [128][256]) + bias2.
// cols: 0..63 r, 64..127 z, 128..191 n_x, 192..255 n_h.  k: [gcn(64)|h(64)].
// ---------------------------------------------------------------------------
__global__ void prep_kernel(const float* __restrict__ Wih,
                            const float* __restrict__ Whh,
                            const float* __restrict__ bih,
                            const float* __restrict__ bhh)
{
    const int n = threadIdx.x;   // 0..255
    for (int k = 0; k < 64; k++)
        g_B2T[k * 256 + n] = (n < 192) ? Wih[n * 64 + k] : 0.0f;
    for (int kk = 0; kk < 64; kk++) {
        float v;
        if      (n < 128) v = Whh[n * 64 + kk];
        else if (n < 192) v = 0.0f;
        else              v = Whh[(n - 64) * 64 + kk];
        g_B2T[(64 + kk) * 256 + n] = v;
    }
    if (n < 128)      g_bias2[n] = bih[n] + bhh[n];
    else if (n < 192) g_bias2[n] = bih[n];
    else              g_bias2[n] = bhh[n - 64];
}

__global__ void transpose_wlin_kernel(const float* __restrict__ Wlin)
{
    const int idx = blockIdx.x * 256 + threadIdx.x;   // k*512 + n
    const int k = idx >> 9;
    const int n = idx & 511;
    g_WlinT[idx] = Wlin[n * 1024 + k];
}

// ---------------------------------------------------------------------------
// Generic GEMM: C = A @ Wk + bias, Wk k-major [K][ldW].
// BM=128, BN=64, BK=32, 128 threads. 8 row-pairs x 4 cols per thread.
// ---------------------------------------------------------------------------
#define GBM 128
#define GBN 64
#define GBK 32

__global__ __launch_bounds__(128)
void gemm_f32x2_kernel(const float* __restrict__ A, int lda,
                       const float* __restrict__ Wk, int ldW, int K,
                       const float* __restrict__ bias,
                       float* __restrict__ C, int ldC)
{
    __shared__ float As [GBK][GBM + 4];   // stride 132
    __shared__ float Bkn[GBK][GBN + 4];   // stride 68

    const int tid = threadIdx.x;
    const int bm = blockIdx.x * GBM;
    const int bn = blockIdx.y * GBN;
    const int w    = tid >> 5;
    const int lane = tid & 31;
    const int ly = lane >> 4;
    const int lx = lane & 15;
    const int rbase = w * 32 + ly * 16;

    u64 acc[8][4];
    #pragma unroll
    for (int i = 0; i < 8; i++)
        #pragma unroll
        for (int j = 0; j < 4; j++) acc[i][j] = 0ull;

    const int lr = tid >> 2;
    const int lk = (tid & 3) * 4;

    for (int k0 = 0; k0 < K; k0 += GBK) {
        #pragma unroll
        for (int half = 0; half < 2; half++) {
            const int kb = k0 + half * 16;
            #pragma unroll
            for (int t = 0; t < 4; t++) {
                int row = lr + 32 * t;
                float4 v = __ldg((const float4*)(A + (size_t)(bm + row) * lda + kb + lk));
                As[half * 16 + lk + 0][row] = v.x;
                As[half * 16 + lk + 1][row] = v.y;
                As[half * 16 + lk + 2][row] = v.z;
                As[half * 16 + lk + 3][row] = v.w;
            }
            #pragma unroll
            for (int t = 0; t < 2; t++) {
                int idx = tid * 2 + t;
                int k = idx >> 4;
                int n4 = (idx & 15) * 4;
                float4 v = __ldg((const float4*)(Wk + (size_t)(kb + k) * ldW + bn + n4));
                *(float4*)&Bkn[half * 16 + k][n4] = v;
            }
        }
        __syncthreads();

        #pragma unroll
        for (int k = 0; k < GBK; k++) {
            u64 av[8], bv[4];
            #pragma unroll
            for (int i = 0; i < 8; i++)
                av[i] = *(const u64*)&As[k][rbase + 2 * i];
            #pragma unroll
            for (int j = 0; j < 4; j++)
                bv[j] = pack2(Bkn[k][lx * 4 + j]);
            #pragma unroll
            for (int i = 0; i < 8; i++)
                #pragma unroll
                for (int j = 0; j < 4; j++)
                    FFMA2(acc[i][j], av[i], bv[j]);
        }
        __syncthreads();
    }

    float bb[4];
    #pragma unroll
    for (int j = 0; j < 4; j++)
        bb[j] = bias ? __ldg(&bias[bn + lx * 4 + j]) : 0.0f;

    #pragma unroll
    for (int i = 0; i < 8; i++) {
        float4 o0, o1;
        o0.x = lo32(acc[i][0]) + bb[0];  o1.x = hi32(acc[i][0]) + bb[0];
        o0.y = lo32(acc[i][1]) + bb[1];  o1.y = hi32(acc[i][1]) + bb[1];
        o0.z = lo32(acc[i][2]) + bb[2];  o1.z = hi32(acc[i][2]) + bb[2];
        o0.w = lo32(acc[i][3]) + bb[3];  o1.w = hi32(acc[i][3]) + bb[3];
        size_t r0 = (size_t)(bm + rbase + 2 * i);
        *(float4*)(C + r0 * ldC + bn + lx * 4)       = o0;
        *(float4*)(C + (r0 + 1) * ldC + bn + lx * 4) = o1;
    }
}

// ---------------------------------------------------------------------------
// GRU mega-kernel v2: per block = 64 nodes = 4 envs, **256 threads** (8 warps,
// 8 rows each -> acc[4][8], half the registers of v1 -> 2x occupancy).
//   1. build 4 normalized 16x16 adjacency matrices (smem atomics)
//   2. gcn = Adj @ xw + bias  -> persistent transposed A-tile sAg[k][row]
//   3. GEMM vs fused B2 (k<64: r,z,nx; k>=64: r,z,nh) + gate epilogue
// Shared layout (46464 B):
//   [0,16896)        sAg float[64][66]
//   [16896,37760)    Bs float[16][260] + Ash float[16][66]  (sxw alias)
//   [37760,42112)    adj float[4][16][17]
//   [42112,42368)    deg float[64]
//   [42368,46464)    sed int[4][256]
// ---------------------------------------------------------------------------
__global__ __launch_bounds__(256, 2)
void gru_mega_kernel(const float* __restrict__ xw,
                     const int* __restrict__ ei,
                     const float* __restrict__ bg,
                     const float* __restrict__ ph,
                     float* __restrict__ hout)
{
    __shared__ __align__(16) char smem_raw[46464];
    float* sAg = (float*)smem_raw;                       // stride 66
    float* Bs  = (float*)(smem_raw + 16896);             // stride 260
    float* Ash = (float*)(smem_raw + 16896 + 16640);     // stride 66
    float* sxw = (float*)(smem_raw + 16896);             // stride 66 (alias)
    float* adj = (float*)(smem_raw + 37760);             // [(e*16+a)*17+b]
    float* deg = (float*)(smem_raw + 42112);
    int*   sed = (int*)  (smem_raw + 42368);             // [e*256 + pos]

    const int tid  = threadIdx.x;                        // 0..255
    const int bm   = blockIdx.x * 64;
    const int env0 = blockIdx.x * 4;
    const int w    = tid >> 5;                           // 0..7
    const int lane = tid & 31;
    const int rbase = w * 8;                             // 8 rows, 4 pairs

    // ---- load edges + stage xw^T + init ------------------------------------
    #pragma unroll
    for (int t = 0; t < 4; t++) {
        int idx = tid + 256 * t;                         // 0..1023
        sed[idx] = __ldg(&ei[(size_t)env0 * 2 * E_PER_G + idx]) & 15;
    }
    #pragma unroll
    for (int t = 0; t < 4; t++) {
        int idx = tid + 256 * t;                         // 0..1023
        int row = idx >> 4, q = idx & 15;
        float4 v = __ldg((const float4*)(xw + (size_t)(bm + row) * 64 + q * 4));
        sxw[(4 * q + 0) * 66 + row] = v.x;
        sxw[(4 * q + 1) * 66 + row] = v.y;
        sxw[(4 * q + 2) * 66 + row] = v.z;
        sxw[(4 * q + 3) * 66 + row] = v.w;
    }
    if (tid < 64) deg[tid] = 1.0f;
    #pragma unroll
    for (int t = 0; t < 5; t++) {
        int i = tid + 256 * t;
        if (i < 4 * 16 * 17) adj[i] = 0.0f;
    }
    __syncthreads();

    // ---- degrees -----------------------------------------------------------
    #pragma unroll
    for (int t = 0; t < 2; t++) {
        int eidx = tid + 256 * t;                        // 0..511
        int e = eidx >> 7, p = eidx & 127;
        atomicAdd(&deg[e * 16 + sed[e * 256 + 128 + p]], 1.0f);
    }
    __syncthreads();

    // ---- adjacency (normalized) + self-loop --------------------------------
    #pragma unroll
    for (int t = 0; t < 2; t++) {
        int eidx = tid + 256 * t;
        int e = eidx >> 7, p = eidx & 127;
        int row = sed[e * 256 + p];
        int col = sed[e * 256 + 128 + p];
        float nm = rsqrtf(deg[e * 16 + row] * deg[e * 16 + col]);
        atomicAdd(&adj[(e * 16 + col) * 17 + row], nm);
    }
    if (tid < 64) {
        int e = tid >> 4, a = tid & 15;
        atomicAdd(&adj[(e * 16 + a) * 17 + a], 1.0f / deg[tid]);
    }
    __syncthreads();

    // ---- gcn = Adj @ xw + bias  -> sAg[k][row] -----------------------------
    {
        const int a_loc = tid & 63;
        const int jq = tid >> 6;                         // 0..3
        const int e = a_loc >> 4, a = a_loc & 15;
        float wrow[16];
        #pragma unroll
        for (int b = 0; b < 16; b++)
            wrow[b] = adj[(e * 16 + a) * 17 + b];
        #pragma unroll
        for (int jj = 0; jj < 16; jj++) {
            int j = jq * 16 + jj;
            float acc0 = __ldg(&bg[j]);
            #pragma unroll
            for (int b = 0; b < 16; b++)
                acc0 += wrow[b] * sxw[j * 66 + e * 16 + b];
            sAg[j * 66 + a_loc] = acc0;
        }
    }
    __syncthreads();   // sxw dead; region2 free for Bs/Ash

    u64 acc[4][8];
    #pragma unroll
    for (int i = 0; i < 4; i++)
        #pragma unroll
        for (int j = 0; j < 8; j++) acc[i][j] = 0ull;

    // ---- phase 1: k in [0,64), A = sAg (resident), gates r,z,nx ------------
    for (int k0 = 0; k0 < 64; k0 += 16) {
        #pragma unroll
        for (int t = 0; t < 4; t++) {                    // stage Bs 16x256
            int idx = tid + 256 * t;                     // 0..1023
            int k = idx >> 6, n4 = (idx & 63) * 4;
            float4 v = *(const float4*)(g_B2T + (size_t)(k0 + k) * 256 + n4);
            *(float4*)&Bs[k * 260 + n4] = v;
        }
        __syncthreads();
        #pragma unroll
        for (int k = 0; k < 16; k++) {
            const float* ar = sAg + (k0 + k) * 66;
            u64 av[4];
            #pragma unroll
            for (int i = 0; i < 4; i++)
                av[i] = *(const u64*)&ar[rbase + 2 * i];
            #pragma unroll
            for (int g = 0; g < 6; g++) {
                u64 bv = pack2(Bs[k * 260 + lane + 32 * g]);
                #pragma unroll
                for (int i = 0; i < 4; i++)
                    FFMA2(acc[i][g], av[i], bv);
            }
        }
        __syncthreads();
    }

    // ---- phase 2: k in [64,128), A = ph (staged), gates r,z,nh -------------
    for (int k0 = 64; k0 < 128; k0 += 16) {
        {   // stage Ash 16x64 from ph (1 float4 per thread)
            const int lr = tid >> 2;                     // 0..63
            const int lk = (tid & 3) * 4;                // 0,4,8,12
            float4 v = __ldg((const float4*)(ph + (size_t)(bm + lr) * 64 + (k0 - 64) + lk));
            Ash[(lk + 0) * 66 + lr] = v.x;
            Ash[(lk + 1) * 66 + lr] = v.y;
            Ash[(lk + 2) * 66 + lr] = v.z;
            Ash[(lk + 3) * 66 + lr] = v.w;
        }
        #pragma unroll
        for (int t = 0; t < 4; t++) {                    // stage Bs
            int idx = tid + 256 * t;
            int k = idx >> 6, n4 = (idx & 63) * 4;
            float4 v = *(const float4*)(g_B2T + (size_t)(k0 + k) * 256 + n4);
            *(float4*)&Bs[k * 260 + n4] = v;
        }
        __syncthreads();
        #pragma unroll
        for (int k = 0; k < 16; k++) {
            const float* ar = Ash + k * 66;
            u64 av[4];
            #pragma unroll
            for (int i = 0; i < 4; i++)
                av[i] = *(const u64*)&ar[rbase + 2 * i];
            #pragma unroll
            for (int gg = 0; gg < 6; gg++) {
                const int g = (gg < 4) ? gg : (gg + 2);  // 0,1,2,3,6,7
                u64 bv = pack2(Bs[k * 260 + lane + 32 * g]);
                #pragma unroll
                for (int i = 0; i < 4; i++)
                    FFMA2(acc[i][g], av[i], bv);
            }
        }
        __syncthreads();
    }

    // ---- gate epilogue -----------------------------------------------------
    #pragma unroll
    for (int half = 0; half < 2; half++) {
        const int c  = lane + 32 * half;
        const int j0 = half;
        const float br = __ldg(&g_bias2[c]);
        const float bz = __ldg(&g_bias2[64 + c]);
        const float bx = __ldg(&g_bias2[128 + c]);
        const float bh = __ldg(&g_bias2[192 + c]);
        #pragma unroll
        for (int i = 0; i < 4; i++) {
            #pragma unroll
            for (int d = 0; d < 2; d++) {
                const size_t node = (size_t)bm + rbase + 2 * i + d;
                float rp = (d ? hi32(acc[i][j0 + 0]) : lo32(acc[i][j0 + 0])) + br;
                float zp = (d ? hi32(acc[i][j0 + 2]) : lo32(acc[i][j0 + 2])) + bz;
                float nx = (d ? hi32(acc[i][j0 + 4]) : lo32(acc[i][j0 + 4])) + bx;
                float nh = (d ? hi32(acc[i][j0 + 6]) : lo32(acc[i][j0 + 6])) + bh;
                float r = 1.0f / (1.0f + expf(-rp));
                float z = 1.0f / (1.0f + expf(-zp));
                float n = tanhf(nx + r * nh);
                float hp = __ldg(&ph[node * 64 + c]);
                hout[node * 64 + c] = (1.0f - z) * n + z * hp;
            }
        }
    }
}

// ---------------------------------------------------------------------------
extern "C" void kernel_launch(void* const* d_in, const int* in_sizes, int n_in,
                              void* d_out, int out_size)
{
    const float* x    = (const float*)d_in[0];
    const int*   ei   = (const int*)d_in[1];
    const float* ph   = (const float*)d_in[2];
    const float* Wg   = (const float*)d_in[3];     // [128][64] k-major
    const float* bg   = (const float*)d_in[4];
    const float* Wih  = (const float*)d_in[5];
    const float* Whh  = (const float*)d_in[6];
    const float* bih  = (const float*)d_in[7];
    const float* bhh  = (const float*)d_in[8];
    const float* Wlin = (const float*)d_in[9];
    const float* blin = (const float*)d_in[10];

    float* out    = (float*)d_out;
    float* logits = out;

    static float *p_xw = nullptr, *p_h = nullptr, *p_WlinT = nullptr;
    if (!p_xw) {
        cudaGetSymbolAddress((void**)&p_xw,    g_xw);
        cudaGetSymbolAddress((void**)&p_h,     g_h);
        cudaGetSymbolAddress((void**)&p_WlinT, g_WlinT);
    }

    const long long need = (long long)NUM_ENVS * (OUT_DIM + FLAT_DIM);
    float* hout = ((long long)out_size >= need)
                      ? out + (size_t)NUM_ENVS * OUT_DIM
                      : p_h;

    prep_kernel<<<1, 256>>>(Wih, Whh, bih, bhh);
    transpose_wlin_kernel<<<(1024 * 512) / 256, 256>>>(Wlin);

    // 1) xw = x @ W_gcn
    {
        dim3 g(N_NODES / GBM, 1);
        gemm_f32x2_kernel<<<g, 128>>>(x, IN_DIM, Wg, GCN_H, IN_DIM, nullptr,
                                      p_xw, GCN_H);
    }

    // 2+3+4) scatter + GRU + gates fused
    gru_mega_kernel<<<N_NODES / 64, 256>>>(p_xw, ei, bg, ph, hout);

    // 5) logits
    {
        dim3 g(NUM_ENVS / GBM, OUT_DIM / GBN);
        gemm_f32x2_kernel<<<g, 128>>>(hout, FLAT_DIM, p_WlinT, OUT_DIM,
                                      FLAT_DIM, blin, logits, OUT_DIM);
    }
}

// round 12
// speedup vs baseline: 9.3006x; 1.1615x over previous
#include <cuda_runtime.h>
#include <cuda_bf16.h>
#include <math.h>
#include <cstdint>

// Problem constants
#define NUM_ENVS   16384
#define NUM_AGENTS 16
#define IN_DIM     128
#define GCN_H      64
#define RNN_H      64
#define E_PER_G    128
#define OUT_DIM    512
#define FLAT_DIM   1024
#define N_NODES    ((size_t)NUM_ENVS * NUM_AGENTS)   // 262144

typedef unsigned long long u64;

// ---- device scratch (static) ----------------------------------------------
__device__ float g_xw  [N_NODES * GCN_H];      // x @ W_gcn
__device__ float g_h   [N_NODES * RNN_H];      // h_new fallback
__device__ float g_B2T [128 * 256];            // fused GRU weights, k-major
__device__ float g_bias2[256];
__device__ __nv_bfloat16 g_Ahi[N_NODES * RNN_H];   // h_new bf16 hi
__device__ __nv_bfloat16 g_Alo[N_NODES * RNN_H];   // h_new bf16 lo
__device__ __nv_bfloat16 g_Whi[(size_t)OUT_DIM * FLAT_DIM]; // W_lin bf16 hi
__device__ __nv_bfloat16 g_Wlo[(size_t)OUT_DIM * FLAT_DIM]; // W_lin bf16 lo

#define FFMA2(acc, a, b) \
    asm("fma.rn.f32x2 %0, %1, %2, %0;" : "+l"(acc) : "l"(a), "l"(b))

__device__ __forceinline__ float lo32(u64 v) { return __uint_as_float((unsigned)v); }
__device__ __forceinline__ float hi32(u64 v) { return __uint_as_float((unsigned)(v >> 32)); }
__device__ __forceinline__ u64 pack2(float v) {
    u64 r; asm("mov.b64 %0, {%1, %1};" : "=l"(r) : "f"(v)); return r;
}
__device__ __forceinline__ uint32_t smem_u32(const void* p) {
    uint32_t a;
    asm("{ .reg .u64 t; cvta.to.shared.u64 t, %1; cvt.u32.u64 %0, t; }"
        : "=r"(a) : "l"(p));
    return a;
}

// ---- mma.sync helpers (base PTX, works under compute_103) ------------------
__device__ __forceinline__ void ldsm_x4(uint32_t* r, uint32_t addr) {
    asm volatile("ldmatrix.sync.aligned.m8n8.x4.shared.b16 {%0,%1,%2,%3}, [%4];"
        : "=r"(r[0]), "=r"(r[1]), "=r"(r[2]), "=r"(r[3]) : "r"(addr));
}
__device__ __forceinline__ void ldsm_x2(uint32_t* r, uint32_t addr) {
    asm volatile("ldmatrix.sync.aligned.m8n8.x2.shared.b16 {%0,%1}, [%2];"
        : "=r"(r[0]), "=r"(r[1]) : "r"(addr));
}
__device__ __forceinline__ void mma_bf16(float* d, const uint32_t* a,
                                         const uint32_t* b) {
    asm volatile("mma.sync.aligned.m16n8k16.row.col.f32.bf16.bf16.f32 "
        "{%0,%1,%2,%3}, {%4,%5,%6,%7}, {%8,%9}, {%0,%1,%2,%3};"
        : "+f"(d[0]), "+f"(d[1]), "+f"(d[2]), "+f"(d[3])
        : "r"(a[0]), "r"(a[1]), "r"(a[2]), "r"(a[3]), "r"(b[0]), "r"(b[1]));
}

// ---------------------------------------------------------------------------
// Prep: fused GRU weights B2 (k-major [128][256]) + bias2.
// ---------------------------------------------------------------------------
__global__ void prep_kernel(const float* __restrict__ Wih,
                            const float* __restrict__ Whh,
                            const float* __restrict__ bih,
                            const float* __restrict__ bhh)
{
    const int n = threadIdx.x;   // 0..255
    for (int k = 0; k < 64; k++)
        g_B2T[k * 256 + n] = (n < 192) ? Wih[n * 64 + k] : 0.0f;
    for (int kk = 0; kk < 64; kk++) {
        float v;
        if      (n < 128) v = Whh[n * 64 + kk];
        else if (n < 192) v = 0.0f;
        else              v = Whh[(n - 64) * 64 + kk];
        g_B2T[(64 + kk) * 256 + n] = v;
    }
    if (n < 128)      g_bias2[n] = bih[n] + bhh[n];
    else if (n < 192) g_bias2[n] = bih[n];
    else              g_bias2[n] = bhh[n - 64];
}

// Split W_lin [512][1024] fp32 -> bf16 hi + lo (residual)
__global__ void split_wlin_kernel(const float* __restrict__ Wlin)
{
    const int idx = blockIdx.x * 256 + threadIdx.x;
    float w = Wlin[idx];
    __nv_bfloat16 hi = __float2bfloat16(w);
    g_Whi[idx] = hi;
    g_Wlo[idx] = __float2bfloat16(w - __bfloat162float(hi));
}

// ---------------------------------------------------------------------------
// Generic GEMM (fp32 f32x2): used for xw only. Wk k-major [K][ldW].
// ---------------------------------------------------------------------------
#define GBM 128
#define GBN 64
#define GBK 32

__global__ __launch_bounds__(128)
void gemm_f32x2_kernel(const float* __restrict__ A, int lda,
                       const float* __restrict__ Wk, int ldW, int K,
                       float* __restrict__ C, int ldC)
{
    __shared__ float As [GBK][GBM + 4];
    __shared__ float Bkn[GBK][GBN + 4];

    const int tid = threadIdx.x;
    const int bm = blockIdx.x * GBM;
    const int bn = blockIdx.y * GBN;
    const int w    = tid >> 5;
    const int lane = tid & 31;
    const int ly = lane >> 4;
    const int lx = lane & 15;
    const int rbase = w * 32 + ly * 16;

    u64 acc[8][4];
    #pragma unroll
    for (int i = 0; i < 8; i++)
        #pragma unroll
        for (int j = 0; j < 4; j++) acc[i][j] = 0ull;

    const int lr = tid >> 2;
    const int lk = (tid & 3) * 4;

    for (int k0 = 0; k0 < K; k0 += GBK) {
        #pragma unroll
        for (int half = 0; half < 2; half++) {
            const int kb = k0 + half * 16;
            #pragma unroll
            for (int t = 0; t < 4; t++) {
                int row = lr + 32 * t;
                float4 v = __ldg((const float4*)(A + (size_t)(bm + row) * lda + kb + lk));
                As[half * 16 + lk + 0][row] = v.x;
                As[half * 16 + lk + 1][row] = v.y;
                As[half * 16 + lk + 2][row] = v.z;
                As[half * 16 + lk + 3][row] = v.w;
            }
            #pragma unroll
            for (int t = 0; t < 2; t++) {
                int idx = tid * 2 + t;
                int k = idx >> 4;
                int n4 = (idx & 15) * 4;
                float4 v = __ldg((const float4*)(Wk + (size_t)(kb + k) * ldW + bn + n4));
                *(float4*)&Bkn[half * 16 + k][n4] = v;
            }
        }
        __syncthreads();

        #pragma unroll
        for (int k = 0; k < GBK; k++) {
            u64 av[8], bv[4];
            #pragma unroll
            for (int i = 0; i < 8; i++)
                av[i] = *(const u64*)&As[k][rbase + 2 * i];
            #pragma unroll
            for (int j = 0; j < 4; j++)
                bv[j] = pack2(Bkn[k][lx * 4 + j]);
            #pragma unroll
            for (int i = 0; i < 8; i++)
                #pragma unroll
                for (int j = 0; j < 4; j++)
                    FFMA2(acc[i][j], av[i], bv[j]);
        }
        __syncthreads();
    }

    #pragma unroll
    for (int i = 0; i < 8; i++) {
        float4 o0, o1;
        o0.x = lo32(acc[i][0]);  o1.x = hi32(acc[i][0]);
        o0.y = lo32(acc[i][1]);  o1.y = hi32(acc[i][1]);
        o0.z = lo32(acc[i][2]);  o1.z = hi32(acc[i][2]);
        o0.w = lo32(acc[i][3]);  o1.w = hi32(acc[i][3]);
        size_t r0 = (size_t)(bm + rbase + 2 * i);
        *(float4*)(C + r0 * ldC + bn + lx * 4)       = o0;
        *(float4*)(C + (r0 + 1) * ldC + bn + lx * 4) = o1;
    }
}

// ---------------------------------------------------------------------------
// GRU mega-kernel (epilogue also emits bf16 hi/lo of h_new).
// ---------------------------------------------------------------------------
__global__ __launch_bounds__(256, 2)
void gru_mega_kernel(const float* __restrict__ xw,
                     const int* __restrict__ ei,
                     const float* __restrict__ bg,
                     const float* __restrict__ ph,
                     float* __restrict__ hout)
{
    __shared__ __align__(16) char smem_raw[46464];
    float* sAg = (float*)smem_raw;
    float* Bs  = (float*)(smem_raw + 16896);
    float* Ash = (float*)(smem_raw + 16896 + 16640);
    float* sxw = (float*)(smem_raw + 16896);
    float* adj = (float*)(smem_raw + 37760);
    float* deg = (float*)(smem_raw + 42112);
    int*   sed = (int*)  (smem_raw + 42368);

    const int tid  = threadIdx.x;
    const int bm   = blockIdx.x * 64;
    const int env0 = blockIdx.x * 4;
    const int w    = tid >> 5;
    const int lane = tid & 31;
    const int rbase = w * 8;

    #pragma unroll
    for (int t = 0; t < 4; t++) {
        int idx = tid + 256 * t;
        sed[idx] = __ldg(&ei[(size_t)env0 * 2 * E_PER_G + idx]) & 15;
    }
    #pragma unroll
    for (int t = 0; t < 4; t++) {
        int idx = tid + 256 * t;
        int row = idx >> 4, q = idx & 15;
        float4 v = __ldg((const float4*)(xw + (size_t)(bm + row) * 64 + q * 4));
        sxw[(4 * q + 0) * 66 + row] = v.x;
        sxw[(4 * q + 1) * 66 + row] = v.y;
        sxw[(4 * q + 2) * 66 + row] = v.z;
        sxw[(4 * q + 3) * 66 + row] = v.w;
    }
    if (tid < 64) deg[tid] = 1.0f;
    #pragma unroll
    for (int t = 0; t < 5; t++) {
        int i = tid + 256 * t;
        if (i < 4 * 16 * 17) adj[i] = 0.0f;
    }
    __syncthreads();

    #pragma unroll
    for (int t = 0; t < 2; t++) {
        int eidx = tid + 256 * t;
        int e = eidx >> 7, p = eidx & 127;
        atomicAdd(&deg[e * 16 + sed[e * 256 + 128 + p]], 1.0f);
    }
    __syncthreads();

    #pragma unroll
    for (int t = 0; t < 2; t++) {
        int eidx = tid + 256 * t;
        int e = eidx >> 7, p = eidx & 127;
        int row = sed[e * 256 + p];
        int col = sed[e * 256 + 128 + p];
        float nm = rsqrtf(deg[e * 16 + row] * deg[e * 16 + col]);
        atomicAdd(&adj[(e * 16 + col) * 17 + row], nm);
    }
    if (tid < 64) {
        int e = tid >> 4, a = tid & 15;
        atomicAdd(&adj[(e * 16 + a) * 17 + a], 1.0f / deg[tid]);
    }
    __syncthreads();

    {
        const int a_loc = tid & 63;
        const int jq = tid >> 6;
        const int e = a_loc >> 4, a = a_loc & 15;
        float wrow[16];
        #pragma unroll
        for (int b = 0; b < 16; b++)
            wrow[b] = adj[(e * 16 + a) * 17 + b];
        #pragma unroll
        for (int jj = 0; jj < 16; jj++) {
            int j = jq * 16 + jj;
            float acc0 = __ldg(&bg[j]);
            #pragma unroll
            for (int b = 0; b < 16; b++)
                acc0 += wrow[b] * sxw[j * 66 + e * 16 + b];
            sAg[j * 66 + a_loc] = acc0;
        }
    }
    __syncthreads();

    u64 acc[4][8];
    #pragma unroll
    for (int i = 0; i < 4; i++)
        #pragma unroll
        for (int j = 0; j < 8; j++) acc[i][j] = 0ull;

    for (int k0 = 0; k0 < 64; k0 += 16) {
        #pragma unroll
        for (int t = 0; t < 4; t++) {
            int idx = tid + 256 * t;
            int k = idx >> 6, n4 = (idx & 63) * 4;
            float4 v = *(const float4*)(g_B2T + (size_t)(k0 + k) * 256 + n4);
            *(float4*)&Bs[k * 260 + n4] = v;
        }
        __syncthreads();
        #pragma unroll
        for (int k = 0; k < 16; k++) {
            const float* ar = sAg + (k0 + k) * 66;
            u64 av[4];
            #pragma unroll
            for (int i = 0; i < 4; i++)
                av[i] = *(const u64*)&ar[rbase + 2 * i];
            #pragma unroll
            for (int g = 0; g < 6; g++) {
                u64 bv = pack2(Bs[k * 260 + lane + 32 * g]);
                #pragma unroll
                for (int i = 0; i < 4; i++)
                    FFMA2(acc[i][g], av[i], bv);
            }
        }
        __syncthreads();
    }

    for (int k0 = 64; k0 < 128; k0 += 16) {
        {
            const int lr = tid >> 2;
            const int lk = (tid & 3) * 4;
            float4 v = __ldg((const float4*)(ph + (size_t)(bm + lr) * 64 + (k0 - 64) + lk));
            Ash[(lk + 0) * 66 + lr] = v.x;
            Ash[(lk + 1) * 66 + lr] = v.y;
            Ash[(lk + 2) * 66 + lr] = v.z;
            Ash[(lk + 3) * 66 + lr] = v.w;
        }
        #pragma unroll
        for (int t = 0; t < 4; t++) {
            int idx = tid + 256 * t;
            int k = idx >> 6, n4 = (idx & 63) * 4;
            float4 v = *(const float4*)(g_B2T + (size_t)(k0 + k) * 256 + n4);
            *(float4*)&Bs[k * 260 + n4] = v;
        }
        __syncthreads();
        #pragma unroll
        for (int k = 0; k < 16; k++) {
            const float* ar = Ash + k * 66;
            u64 av[4];
            #pragma unroll
            for (int i = 0; i < 4; i++)
                av[i] = *(const u64*)&ar[rbase + 2 * i];
            #pragma unroll
            for (int gg = 0; gg < 6; gg++) {
                const int g = (gg < 4) ? gg : (gg + 2);
                u64 bv = pack2(Bs[k * 260 + lane + 32 * g]);
                #pragma unroll
                for (int i = 0; i < 4; i++)
                    FFMA2(acc[i][g], av[i], bv);
            }
        }
        __syncthreads();
    }

    #pragma unroll
    for (int half = 0; half < 2; half++) {
        const int c  = lane + 32 * half;
        const int j0 = half;
        const float br = __ldg(&g_bias2[c]);
        const float bz = __ldg(&g_bias2[64 + c]);
        const float bx = __ldg(&g_bias2[128 + c]);
        const float bh = __ldg(&g_bias2[192 + c]);
        #pragma unroll
        for (int i = 0; i < 4; i++) {
            #pragma unroll
            for (int d = 0; d < 2; d++) {
                const size_t node = (size_t)bm + rbase + 2 * i + d;
                float rp = (d ? hi32(acc[i][j0 + 0]) : lo32(acc[i][j0 + 0])) + br;
                float zp = (d ? hi32(acc[i][j0 + 2]) : lo32(acc[i][j0 + 2])) + bz;
                float nx = (d ? hi32(acc[i][j0 + 4]) : lo32(acc[i][j0 + 4])) + bx;
                float nh = (d ? hi32(acc[i][j0 + 6]) : lo32(acc[i][j0 + 6])) + bh;
                float r = 1.0f / (1.0f + expf(-rp));
                float z = 1.0f / (1.0f + expf(-zp));
                float n = tanhf(nx + r * nh);
                float hp = __ldg(&ph[node * 64 + c]);
                float hv = (1.0f - z) * n + z * hp;
                hout[node * 64 + c] = hv;
                __nv_bfloat16 hi = __float2bfloat16(hv);
                g_Ahi[node * 64 + c] = hi;
                g_Alo[node * 64 + c] = __float2bfloat16(hv - __bfloat162float(hi));
            }
        }
    }
}

// ---------------------------------------------------------------------------
// Logits via mma.sync bf16-split GEMM (HMMA path; compiles under compute_103).
// Block: 128M x 128N, K staged 32/iter (hi+lo for A and B = 40KB smem).
// 8 warps as 4Mx2N; warp = 32M x 64N = 2x8 m16n8k16 tiles.
// Per k16: acc += Ahi*Bhi + Ahi*Blo + Alo*Bhi  (fp32 accumulators).
// Smem rows padded to 40 bf16 (80B) -> conflict-free ldmatrix.
// ---------------------------------------------------------------------------
#define LPAD 40

__global__ __launch_bounds__(256)
void logits_mma_kernel(float* __restrict__ C, const float* __restrict__ bias)
{
    __shared__ __nv_bfloat16 sAhi[128 * LPAD];
    __shared__ __nv_bfloat16 sAlo[128 * LPAD];
    __shared__ __nv_bfloat16 sBhi[128 * LPAD];
    __shared__ __nv_bfloat16 sBlo[128 * LPAD];

    const int tid  = threadIdx.x;
    const int wid  = tid >> 5;
    const int lane = tid & 31;
    const int wm = wid >> 1;             // 0..3  (M quadrant, 32 rows)
    const int wn = wid & 1;              // 0..1  (N half, 64 cols)
    const int bm0 = blockIdx.x * 128;
    const int bn0 = blockIdx.y * 128;

    const uint32_t aAhi = smem_u32(sAhi);
    const uint32_t aAlo = smem_u32(sAlo);
    const uint32_t aBhi = smem_u32(sBhi);
    const uint32_t aBlo = smem_u32(sBlo);

    float acc[2][8][4];
    #pragma unroll
    for (int mt = 0; mt < 2; mt++)
        #pragma unroll
        for (int nt = 0; nt < 8; nt++)
            #pragma unroll
            for (int q = 0; q < 4; q++) acc[mt][nt][q] = 0.0f;

    // ldmatrix source offsets (element units)
    const int arow = (lane & 15);              // + wm*32 + mt*16
    const int acol8 = (lane >> 4) * 8;         // 0 or 8 (+ks)
    const int brow = (lane & 7);               // + wn*64 + nt*8
    const int bcol8 = ((lane >> 3) & 1) * 8;   // 0 or 8 (+ks)

    for (int kb = 0; kb < FLAT_DIM; kb += 32) {
        // stage A/B hi+lo: 128 rows x 32 bf16 each (2 uint4 per thread/tile)
        #pragma unroll
        for (int t = 0; t < 2; t++) {
            int idx = tid + 256 * t;           // 0..511
            int row = idx >> 2, q = idx & 3;
            int soff = row * LPAD + q * 8;     // element offset, 16B aligned
            size_t ga = (size_t)(bm0 + row) * FLAT_DIM + kb + q * 8;
            size_t gb = (size_t)(bn0 + row) * FLAT_DIM + kb + q * 8;
            *(uint4*)&sAhi[soff] = __ldg((const uint4*)(g_Ahi + ga));
            *(uint4*)&sAlo[soff] = __ldg((const uint4*)(g_Alo + ga));
            *(uint4*)&sBhi[soff] = __ldg((const uint4*)(g_Whi + gb));
            *(uint4*)&sBlo[soff] = __ldg((const uint4*)(g_Wlo + gb));
        }
        __syncthreads();

        #pragma unroll
        for (int ks = 0; ks < 32; ks += 16) {
            uint32_t ahi[2][4], alo[2][4];
            #pragma unroll
            for (int mt = 0; mt < 2; mt++) {
                int eoff = (wm * 32 + mt * 16 + arow) * LPAD + ks + acol8;
                ldsm_x4(ahi[mt], aAhi + eoff * 2);
                ldsm_x4(alo[mt], aAlo + eoff * 2);
            }
            #pragma unroll
            for (int nt = 0; nt < 8; nt++) {
                int eoff = (wn * 64 + nt * 8 + brow) * LPAD + ks + bcol8;
                uint32_t bhi[2], blo[2];
                ldsm_x2(bhi, aBhi + eoff * 2);
                ldsm_x2(blo, aBlo + eoff * 2);
                #pragma unroll
                for (int mt = 0; mt < 2; mt++) {
                    mma_bf16(acc[mt][nt], ahi[mt], bhi);
                    mma_bf16(acc[mt][nt], ahi[mt], blo);
                    mma_bf16(acc[mt][nt], alo[mt], bhi);
                }
            }
        }
        __syncthreads();
    }

    // Epilogue: c frag m16n8 layout: thread t -> rows (t>>2, t>>2+8),
    // cols (t&3)*2, +1.
    const int erow = lane >> 2;
    const int ecol = (lane & 3) * 2;
    #pragma unroll
    for (int mt = 0; mt < 2; mt++) {
        #pragma unroll
        for (int nt = 0; nt < 8; nt++) {
            int col = bn0 + wn * 64 + nt * 8 + ecol;
            float b0 = __ldg(&bias[col]);
            float b1 = __ldg(&bias[col + 1]);
            size_t r0 = (size_t)(bm0 + wm * 32 + mt * 16 + erow);
            float2 v0 = make_float2(acc[mt][nt][0] + b0, acc[mt][nt][1] + b1);
            float2 v1 = make_float2(acc[mt][nt][2] + b0, acc[mt][nt][3] + b1);
            *(float2*)(C + r0 * OUT_DIM + col)       = v0;
            *(float2*)(C + (r0 + 8) * OUT_DIM + col) = v1;
        }
    }
}

// ---------------------------------------------------------------------------
extern "C" void kernel_launch(void* const* d_in, const int* in_sizes, int n_in,
                              void* d_out, int out_size)
{
    const float* x    = (const float*)d_in[0];
    const int*   ei   = (const int*)d_in[1];
    const float* ph   = (const float*)d_in[2];
    const float* Wg   = (const float*)d_in[3];     // [128][64] k-major
    const float* bg   = (const float*)d_in[4];
    const float* Wih  = (const float*)d_in[5];
    const float* Whh  = (const float*)d_in[6];
    const float* bih  = (const float*)d_in[7];
    const float* bhh  = (const float*)d_in[8];
    const float* Wlin = (const float*)d_in[9];
    const float* blin = (const float*)d_in[10];

    float* out    = (float*)d_out;
    float* logits = out;

    static float *p_xw = nullptr, *p_h = nullptr;
    if (!p_xw) {
        cudaGetSymbolAddress((void**)&p_xw, g_xw);
        cudaGetSymbolAddress((void**)&p_h,  g_h);
    }

    const long long need = (long long)NUM_ENVS * (OUT_DIM + FLAT_DIM);
    float* hout = ((long long)out_size >= need)
                      ? out + (size_t)NUM_ENVS * OUT_DIM
                      : p_h;

    prep_kernel<<<1, 256>>>(Wih, Whh, bih, bhh);
    split_wlin_kernel<<<(OUT_DIM * FLAT_DIM) / 256, 256>>>(Wlin);

    // 1) xw = x @ W_gcn
    {
        dim3 g(N_NODES / GBM, 1);
        gemm_f32x2_kernel<<<g, 128>>>(x, IN_DIM, Wg, GCN_H, IN_DIM,
                                      p_xw, GCN_H);
    }

    // 2+3+4) scatter + GRU + gates fused (also emits bf16 hi/lo of h)
    gru_mega_kernel<<<N_NODES / 64, 256>>>(p_xw, ei, bg, ph, hout);

    // 5) logits via mma.sync bf16-split GEMM
    {
        dim3 g(NUM_ENVS / 128, OUT_DIM / 128);
        logits_mma_kernel<<<g, 256>>>(logits, blin);
    }
}